// round 14
// baseline (speedup 1.0000x reference)
#include <cuda_runtime.h>
#include <cuda_fp16.h>
#include <cstdint>

#define B_    8
#define N_    1024
#define T_    8
#define CIN   64
#define CO    64
#define COLS  512          // T_ * CO
#define NB    (B_ * N_)    // 8192
#define L2E   1.4426950408889634f     // log2(e)
#define NEGH  (-0.72134752044448170f) // -0.5*log2(e)

// ---------------- scratch (static device arrays; no allocation) ----------------
static __device__ __align__(16) float g_rspart[4][NB];      // rowsum partials (k-quarters)
static __device__ __align__(16) float g_cf[NB * T_];        // [b][n][t] exp(-ptd - tsq/2)
static __device__ __align__(16) float g_u [NB * T_];        // [b][n][t] exp(+ptd)
static __device__ __align__(16) float g_kB[CIN * COLS];     // [c][t*64+o]
// E as fp16 m16n8k16 A-fragments: [b][nt(8)][u(64)][mt(8)][lane(32)] uint4
static __device__ __align__(16) uint4 g_E4h[B_ * 8 * 64 * 256];
// Ht as fp16 B-fragments: [b][ch2(2)][u(64)][n8g(32)][lane(32)] uint2
static __device__ __align__(16) uint2 g_Hth[B_ * 2 * 64 * 32 * 32];
static __device__ __align__(16) float g_preP[4][NB * CO];   // per-ch partial planes
static __device__ __align__(16) float g_part [256 * CO];
static __device__ __align__(16) float g_part2[256 * CO];
static __device__ int g_ctr;

// ---------------- helpers ----------------
__device__ __forceinline__ float to_tf32(float x) {
    float r;
    asm("cvt.rna.tf32.f32 %0, %1;" : "=f"(r) : "f"(x));
    return r;
}
__device__ __forceinline__ float ex2f(float x) {
    float r;
    asm("ex2.approx.ftz.f32 %0, %1;" : "=f"(r) : "f"(x));
    return r;
}
__device__ __forceinline__ uint32_t h2pack(float lo, float hi) {
    uint32_t r;
    asm("cvt.rn.f16x2.f32 %0, %1, %2;" : "=r"(r) : "f"(hi), "f"(lo));
    return r;
}
__device__ __forceinline__ uint32_t smem_u32(const void* p) {
    uint32_t a;
    asm("{ .reg .u64 t; cvta.to.shared.u64 t, %1; cvt.u32.u64 %0, t; }" : "=r"(a) : "l"(p));
    return a;
}
__device__ __forceinline__ void cp16(uint32_t s, const void* g) {
    asm volatile("cp.async.cg.shared.global [%0], [%1], 16;" :: "r"(s), "l"(g) : "memory");
}
#define CP_COMMIT() asm volatile("cp.async.commit_group;" ::: "memory")
#define CP_WAIT(n)  asm volatile("cp.async.wait_group %0;" :: "n"(n) : "memory")

// mma.sync m16n8k8 tf32 (Ht phase)
__device__ __forceinline__ void mma1688(float* c, const uint32_t* a, const uint32_t* b2) {
    asm volatile(
        "mma.sync.aligned.m16n8k8.row.col.f32.tf32.tf32.f32 "
        "{%0,%1,%2,%3}, {%4,%5,%6,%7}, {%8,%9}, {%0,%1,%2,%3};"
        : "+f"(c[0]), "+f"(c[1]), "+f"(c[2]), "+f"(c[3])
        : "r"(a[0]), "r"(a[1]), "r"(a[2]), "r"(a[3]), "r"(b2[0]), "r"(b2[1]));
}
// mma.sync m16n8k16 fp16 with f32 accum (mainloop)
__device__ __forceinline__ void mma16816(float* c, const uint4 a, const uint2 b) {
    asm volatile(
        "mma.sync.aligned.m16n8k16.row.col.f32.f16.f16.f32 "
        "{%0,%1,%2,%3}, {%4,%5,%6,%7}, {%8,%9}, {%0,%1,%2,%3};"
        : "+f"(c[0]), "+f"(c[1]), "+f"(c[2]), "+f"(c[3])
        : "r"(a.x), "r"(a.y), "r"(a.z), "r"(a.w), "r"(b.x), "r"(b.y));
}

// ---------------- K0: E gen (fp16 A-frags) + rowsum quarters + cf/u + kB copy --
// grid 256: b = bx>>5, nt = (bx>>2)&7, kq = bx&3 (u units kq*16 .. +15)
__global__ __launch_bounds__(512) void k_prepE(const float* __restrict__ pts,
                                               const float* __restrict__ trans,
                                               const float* __restrict__ kt) {
    __shared__ float4 pts4[N_];
    __shared__ float4 tr4[T_];
    __shared__ float red[128 * 9];

    int bx = blockIdx.x;
    int b  = bx >> 5;
    int nt = (bx >> 2) & 7;
    int kq = bx & 3;
    int n0 = nt * 128;
    int tid = threadIdx.x;

    if (bx == 0 && tid == 0) g_ctr = 0;   // reset barrier counter for k_main

    if (bx < 16) {
        #pragma unroll
        for (int q = 0; q < 4; ++q) {
            int i = bx * 2048 + q * 512 + tid;
            int c = i >> 9;
            int t = (i >> 6) & 7;
            int o = i & 63;
            g_kB[i] = kt[(o * CIN + c) * T_ + t];
        }
    }

    for (int n = tid; n < N_; n += 512) {
        const float* pp = pts + (b * N_ + n) * 3;
        float x = pp[0], y = pp[1], z = pp[2];
        pts4[n] = make_float4(x, y, z, NEGH * (x * x + y * y + z * z));
    }
    if (tid < T_) {
        const float* tp = trans + (b * T_ + tid) * 3;
        float x = tp[0], y = tp[1], z = tp[2];
        tr4[tid] = make_float4(x, y, z, x * x + y * y + z * z);
    }
    __syncthreads();

    int lane = tid & 31;
    int w    = tid >> 5;
    int mt   = w >> 1;
    int upar = w & 1;
    int r    = lane >> 2;
    int cq   = (lane & 3) * 2;

    float4 pr  = pts4[n0 + mt * 16 + r];
    float4 pr8 = pts4[n0 + mt * 16 + r + 8];

    float sum_r = 0.0f, sum_r8 = 0.0f;
    uint4* ebase = g_E4h + (size_t)(b * 8 + nt) * 64 * 256;

    #pragma unroll 4
    for (int i = 0; i < 8; ++i) {
        int u = kq * 16 + upar + 2 * i;
        int m = u * 16 + cq;
        float4 q0 = pts4[m], q1 = pts4[m + 1];
        float4 q8 = pts4[m + 8], q9 = pts4[m + 9];

        float e_r_0  = ex2f(fmaf(fmaf(pr.z, q0.z, fmaf(pr.y, q0.y, pr.x * q0.x)), L2E, pr.w + q0.w));
        float e_r_1  = ex2f(fmaf(fmaf(pr.z, q1.z, fmaf(pr.y, q1.y, pr.x * q1.x)), L2E, pr.w + q1.w));
        float e_r_8  = ex2f(fmaf(fmaf(pr.z, q8.z, fmaf(pr.y, q8.y, pr.x * q8.x)), L2E, pr.w + q8.w));
        float e_r_9  = ex2f(fmaf(fmaf(pr.z, q9.z, fmaf(pr.y, q9.y, pr.x * q9.x)), L2E, pr.w + q9.w));
        float e_s_0  = ex2f(fmaf(fmaf(pr8.z, q0.z, fmaf(pr8.y, q0.y, pr8.x * q0.x)), L2E, pr8.w + q0.w));
        float e_s_1  = ex2f(fmaf(fmaf(pr8.z, q1.z, fmaf(pr8.y, q1.y, pr8.x * q1.x)), L2E, pr8.w + q1.w));
        float e_s_8  = ex2f(fmaf(fmaf(pr8.z, q8.z, fmaf(pr8.y, q8.y, pr8.x * q8.x)), L2E, pr8.w + q8.w));
        float e_s_9  = ex2f(fmaf(fmaf(pr8.z, q9.z, fmaf(pr8.y, q9.y, pr8.x * q9.x)), L2E, pr8.w + q9.w));

        sum_r  += (e_r_0 + e_r_1) + (e_r_8 + e_r_9);
        sum_r8 += (e_s_0 + e_s_1) + (e_s_8 + e_s_9);

        uint4 frag;
        frag.x = h2pack(e_r_0, e_r_1);
        frag.y = h2pack(e_s_0, e_s_1);
        frag.z = h2pack(e_r_8, e_r_9);
        frag.w = h2pack(e_s_8, e_s_9);
        ebase[(size_t)u * 256 + mt * 32 + lane] = frag;
    }

    int col = upar * 4 + (lane & 3);
    red[(mt * 16 + r    ) * 9 + col] = sum_r;
    red[(mt * 16 + r + 8) * 9 + col] = sum_r8;
    __syncthreads();

    if (tid < 128) {
        float rs = 0.0f;
        #pragma unroll
        for (int c = 0; c < 8; ++c) rs += red[tid * 9 + c];
        g_rspart[kq][b * N_ + n0 + tid] = rs;
        if (kq == 0) {
            float4 pn = pts4[n0 + tid];
            #pragma unroll
            for (int t = 0; t < T_; ++t) {
                float4 tv = tr4[t];
                float ptd = fmaf(pn.z, tv.z, fmaf(pn.y, tv.y, pn.x * tv.x));
                g_cf[(b * N_ + n0 + tid) * T_ + t] = __expf(-ptd - 0.5f * tv.w);
                g_u [(b * N_ + n0 + tid) * T_ + t] = __expf(ptd);
            }
        }
    }
}

// ---------------- K1: Ht phase + fp16 HMMA GEMM + barriers + fused BN/ReLU ----
// grid 256 (2 CTA/SM, ALL resident): bx -> (b=bx>>5, X=(bx>>2)&7, Y=bx&3).
// Ht phase: (b, mt=X, ct=Y).  GEMM: (b, nt=X, ch=Y).  128 thr, smem 96KB.
#define WS_STRIDE 68
#define KB_STRIDE 136
#define HC_STRIDE 132
#define RST 68
__global__ __launch_bounds__(128, 2) void k_main(float* __restrict__ out,
                                                 const float* __restrict__ gamma,
                                                 const float* __restrict__ beta,
                                                 const float* __restrict__ func) {
    extern __shared__ float sm[];
    uint32_t sbase = smem_u32(sm);

    int bx = blockIdx.x;
    int b  = bx >> 5;
    int X  = (bx >> 2) & 7;
    int Y  = bx & 3;
    int tid = threadIdx.x;
    int wid = tid >> 5, lane = tid & 31;
    int mw = wid & 1, nw = wid >> 1;

    // ======================= PHASE A: Ht tile (b, mt=X, ct=Y) =================
    {
        int mt = X, ct = Y;
        int m0 = mt * 128, c0 = ct * 128;
        float* w_s  = sm;                    // [128][68]
        float* kBs  = sm + 128 * WS_STRIDE;  // [64][136]
        float* rinv = sm + 17408;            // [128] (above canonical region)

        if (tid == 0 && bx == 0) { }         // (barrier ctr already reset by prepE)
        {
            int idx = b * N_ + m0 + tid;
            rinv[tid] = 1.0f / (g_rspart[0][idx] + g_rspart[1][idx]
                              + g_rspart[2][idx] + g_rspart[3][idx]);
        }
        __syncthreads();

        for (int i = tid; i < 128 * 16; i += 128) {
            int m = i >> 4, c4 = i & 15;
            float4 v = *(const float4*)(func + (b * N_ + m0 + m) * CIN + c4 * 4);
            float r = rinv[m];
            v.x = to_tf32(v.x * r); v.y = to_tf32(v.y * r);
            v.z = to_tf32(v.z * r); v.w = to_tf32(v.w * r);
            *(float4*)(w_s + m * WS_STRIDE + c4 * 4) = v;
        }
        for (int i = tid; i < 64 * 32; i += 128) {
            int c = i >> 5, j = i & 31;
            float4 v = *(const float4*)(g_kB + c * COLS + c0 + j * 4);
            v.x = to_tf32(v.x); v.y = to_tf32(v.y);
            v.z = to_tf32(v.z); v.w = to_tf32(v.w);
            *(float4*)(kBs + c * KB_STRIDE + j * 4) = v;
        }
        __syncthreads();

        float c_[4][8][4];
        #pragma unroll
        for (int i = 0; i < 4; ++i)
            #pragma unroll
            for (int j = 0; j < 8; ++j)
                #pragma unroll
                for (int q = 0; q < 4; ++q) c_[i][j][q] = 0.0f;

        int ar = (lane >> 2), ac = (lane & 3);
        #pragma unroll
        for (int k8 = 0; k8 < 8; ++k8) {
            uint32_t a[4][4];
            #pragma unroll
            for (int mi = 0; mi < 4; ++mi) {
                int row = mw * 64 + mi * 16 + ar;
                int col = k8 * 8 + ac;
                a[mi][0] = __float_as_uint(w_s[row * WS_STRIDE + col]);
                a[mi][1] = __float_as_uint(w_s[(row + 8) * WS_STRIDE + col]);
                a[mi][2] = __float_as_uint(w_s[row * WS_STRIDE + col + 4]);
                a[mi][3] = __float_as_uint(w_s[(row + 8) * WS_STRIDE + col + 4]);
            }
            uint32_t bv[8][2];
            #pragma unroll
            for (int nj = 0; nj < 8; ++nj) {
                int kk = k8 * 8 + ac;
                int col = nw * 64 + nj * 8 + ar;
                bv[nj][0] = __float_as_uint(kBs[kk * KB_STRIDE + col]);
                bv[nj][1] = __float_as_uint(kBs[(kk + 4) * KB_STRIDE + col]);
            }
            #pragma unroll
            for (int mi = 0; mi < 4; ++mi)
                #pragma unroll
                for (int nj = 0; nj < 8; ++nj)
                    mma1688(c_[mi][nj], a[mi], bv[nj]);
        }
        __syncthreads();   // staging dead; reuse smem as canonical tile

        #pragma unroll
        for (int mi = 0; mi < 4; ++mi)
            #pragma unroll
            for (int nj = 0; nj < 8; ++nj)
                #pragma unroll
                for (int q = 0; q < 4; ++q) {
                    int row = mw * 64 + mi * 16 + ar + ((q >> 1) * 8);
                    int col = nw * 64 + nj * 8 + ac * 2 + (q & 1);
                    sm[row * HC_STRIDE + col] = c_[mi][nj][q];
                }
        __syncthreads();

        // pack to fp16 B-fragments (two ty-halves, 128 threads)
        int tx = tid & 15;
        int jt_g = ct * 16 + tx;
        int t = jt_g >> 3;
        int ch2 = ct >> 1;
        int n8g = (ct & 1) * 16 + tx;
        char* hb = (char*)g_Hth;
        #pragma unroll
        for (int h = 0; h < 2; ++h) {
            int ty = h * 8 + (tid >> 4);
            float cf_i[8];
            #pragma unroll
            for (int i = 0; i < 8; ++i)
                cf_i[i] = g_cf[(b * N_ + m0 + ty * 8 + i) * T_ + t];
            int u   = mt * 8 + (ty >> 1);
            int sel = ty & 1;
            size_t base_idx = ((size_t)((b * 2 + ch2) * 64 + u) * 32 + n8g) * 32;
            #pragma unroll
            for (int jj = 0; jj < 8; ++jj) {
                float v[8];
                #pragma unroll
                for (int i = 0; i < 8; ++i)
                    v[i] = sm[(ty * 8 + i) * HC_STRIDE + tx * 8 + jj] * cf_i[i];
                #pragma unroll
                for (int ip = 0; ip < 4; ++ip) {
                    uint32_t hv = h2pack(v[2 * ip], v[2 * ip + 1]);
                    size_t idx = base_idx + jj * 4 + ip;
                    *(uint32_t*)(hb + idx * 8 + sel * 4) = hv;
                }
            }
        }
    }

    // ---- device-wide barrier #0: all Ht fragments written ----
    __threadfence();
    __syncthreads();
    if (tid == 0) {
        atomicAdd(&g_ctr, 1);
        while (atomicAdd(&g_ctr, 0) < 256) { __nanosleep(32); }
    }
    __syncthreads();

    // ======================= PHASE B: GEMM (b, nt=X, ch=Y) ====================
    int nt = X, ch = Y;
    int ch2 = ch >> 1, chH = ch & 1;
    int n0 = nt * 128;
    int skew = (bx & 1) * 8;

    const char* EA = (const char*)(g_E4h + (size_t)(b * 8 + nt) * 64 * 256);
    const char* HB = (const char*)(g_Hth + (size_t)(b * 2 + ch2) * 64 * 1024) + chH * 4096;
    uint32_t sA = sbase;              // 3 x 16384 B
    uint32_t sB = sbase + 49152;      // 3 x 16384 B

    auto issue = [&](int s) {
        int buf = s % 3;
        int u0 = ((s + skew) & 15) * 4;
        #pragma unroll
        for (int p = 0; p < 8; ++p) {
            int idx = p * 128 + tid;
            int ul = idx >> 8, rem = (idx & 255) * 16;
            cp16(sA + buf * 16384 + idx * 16, EA + (size_t)(u0 + ul) * 4096 + rem);
            cp16(sB + buf * 16384 + idx * 16, HB + (size_t)(u0 + ul) * 8192 + rem);
        }
        CP_COMMIT();
    };

    issue(0); issue(1);

    float c_[4][8][4];
    #pragma unroll
    for (int i = 0; i < 4; ++i)
        #pragma unroll
        for (int j = 0; j < 8; ++j)
            #pragma unroll
            for (int q = 0; q < 4; ++q) c_[i][j][q] = 0.0f;

    for (int kc = 0; kc < 16; ++kc) {
        if (kc < 14) { CP_WAIT(1); } else { CP_WAIT(0); }
        __syncthreads();

        int buf = kc % 3;
        const uint4* Au = (const uint4*)(sm) + buf * 1024;
        const uint2* Bu = (const uint2*)(sm + 12288) + buf * 2048;

        #pragma unroll
        for (int ul = 0; ul < 4; ++ul) {
            uint4 a[4];
            #pragma unroll
            for (int mi = 0; mi < 4; ++mi)
                a[mi] = Au[(ul * 8 + mw * 4 + mi) * 32 + lane];
            uint2 bv[8];
            #pragma unroll
            for (int nj = 0; nj < 8; ++nj)
                bv[nj] = Bu[(ul * 16 + nw * 8 + nj) * 32 + lane];
            #pragma unroll
            for (int mi = 0; mi < 4; ++mi)
                #pragma unroll
                for (int nj = 0; nj < 8; ++nj)
                    mma16816(c_[mi][nj], a[mi], bv[nj]);
        }

        if (kc < 14) issue(kc + 2);
    }

    // ---- GEMM epilogue: scale by u_t, smem-reduce the CTA's two t's, write plane
    __syncthreads();
    {
        int t = ch * 2 + nw;
        float* red = sm + mw * 64 * RST;

        if (nw == 0) {
            #pragma unroll
            for (int mi = 0; mi < 4; ++mi) {
                #pragma unroll
                for (int ro = 0; ro < 2; ++ro) {
                    int rloc = mi * 16 + (lane >> 2) + ro * 8;
                    float u = g_u[(b * N_ + n0 + mw * 64 + rloc) * T_ + t];
                    #pragma unroll
                    for (int nj = 0; nj < 8; ++nj) {
                        float2 v;
                        v.x = c_[mi][nj][ro * 2 + 0] * u;
                        v.y = c_[mi][nj][ro * 2 + 1] * u;
                        *(float2*)(red + rloc * RST + nj * 8 + (lane & 3) * 2) = v;
                    }
                }
            }
        }
        __syncthreads();
        if (nw == 1) {
            #pragma unroll
            for (int mi = 0; mi < 4; ++mi) {
                #pragma unroll
                for (int ro = 0; ro < 2; ++ro) {
                    int rloc = mi * 16 + (lane >> 2) + ro * 8;
                    int n = n0 + mw * 64 + rloc;
                    float u = g_u[(b * N_ + n) * T_ + t];
                    float* dst = g_preP[ch] + (size_t)(b * N_ + n) * CO + (lane & 3) * 2;
                    #pragma unroll
                    for (int nj = 0; nj < 8; ++nj) {
                        float2 p = *(const float2*)(red + rloc * RST + nj * 8 + (lane & 3) * 2);
                        float2 v;
                        v.x = fmaf(c_[mi][nj][ro * 2 + 0], u, p.x);
                        v.y = fmaf(c_[mi][nj][ro * 2 + 1], u, p.y);
                        *(float2*)(dst + nj * 8) = v;
                    }
                }
            }
        }
    }

    // ---- device-wide barrier #1: all plane writes done ----
    __threadfence();
    __syncthreads();
    if (tid == 0) {
        atomicAdd(&g_ctr, 1);
        while (atomicAdd(&g_ctr, 0) < 512) { __nanosleep(32); }
    }
    __syncthreads();

    // ---- post phase 1: sum 4 planes for this block's 32 rows (L2-hot) ----
    float4* shs  = (float4*)sm;          // [16][8]
    float4* shs2 = (float4*)sm + 128;    // [16][8]
    float*  ssc  = sm + 1024;
    float*  sbi  = sm + 1088;
    int base4 = bx * 512;                // float4 index of this block's 32 rows
    int oq  = tid & 15;                  // channel quad
    int grp = tid >> 4;                  // 0..7

    const float4* P0 = (const float4*)g_preP[0];
    const float4* P1 = (const float4*)g_preP[1];
    const float4* P2 = (const float4*)g_preP[2];
    const float4* P3 = (const float4*)g_preP[3];

    float4 pv[4];
    float4 s  = make_float4(0.f, 0.f, 0.f, 0.f);
    float4 s2 = make_float4(0.f, 0.f, 0.f, 0.f);
    #pragma unroll
    for (int q = 0; q < 4; ++q) {
        int idx = base4 + q * 128 + tid;
        float4 a  = __ldcg(&P0[idx]);
        float4 b1 = __ldcg(&P1[idx]);
        float4 c  = __ldcg(&P2[idx]);
        float4 d  = __ldcg(&P3[idx]);
        float4 p;
        p.x = (a.x + b1.x) + (c.x + d.x);
        p.y = (a.y + b1.y) + (c.y + d.y);
        p.z = (a.z + b1.z) + (c.z + d.z);
        p.w = (a.w + b1.w) + (c.w + d.w);
        pv[q] = p;
        s.x += p.x; s.y += p.y; s.z += p.z; s.w += p.w;
        s2.x += p.x * p.x; s2.y += p.y * p.y; s2.z += p.z * p.z; s2.w += p.w * p.w;
    }
    shs [oq * 8 + grp] = s;
    shs2[oq * 8 + grp] = s2;
    __syncthreads();
    if (tid < 16) {
        float4 ts  = shs [tid * 8], ts2 = shs2[tid * 8];
        #pragma unroll
        for (int g = 1; g < 8; ++g) {
            float4 a = shs[tid * 8 + g], b1 = shs2[tid * 8 + g];
            ts.x += a.x; ts.y += a.y; ts.z += a.z; ts.w += a.w;
            ts2.x += b1.x; ts2.y += b1.y; ts2.z += b1.z; ts2.w += b1.w;
        }
        ((float4*)g_part )[bx * 16 + tid] = ts;
        ((float4*)g_part2)[bx * 16 + tid] = ts2;
    }

    // ---- device-wide barrier #2: all stat partials done ----
    __threadfence();
    __syncthreads();
    if (tid == 0) {
        atomicAdd(&g_ctr, 1);
        while (atomicAdd(&g_ctr, 0) < 768) { __nanosleep(32); }
    }
    __syncthreads();

    // ---- post phase 2: reduce 256 partials, compute scale/bias ----
    {
        const float4* G1 = (const float4*)g_part;
        const float4* G2 = (const float4*)g_part2;
        float4 ps  = make_float4(0.f, 0.f, 0.f, 0.f);
        float4 ps2 = make_float4(0.f, 0.f, 0.f, 0.f);
        for (int i = grp; i < 256; i += 8) {
            float4 a  = __ldcg(&G1[i * 16 + oq]);
            float4 b1 = __ldcg(&G2[i * 16 + oq]);
            ps.x += a.x; ps.y += a.y; ps.z += a.z; ps.w += a.w;
            ps2.x += b1.x; ps2.y += b1.y; ps2.z += b1.z; ps2.w += b1.w;
        }
        shs [oq * 8 + grp] = ps;
        shs2[oq * 8 + grp] = ps2;
        __syncthreads();
        if (tid < 16) {
            float4 ts  = shs [tid * 8], ts2 = shs2[tid * 8];
            #pragma unroll
            for (int g = 1; g < 8; ++g) {
                float4 a = shs[tid * 8 + g], b1 = shs2[tid * 8 + g];
                ts.x += a.x; ts.y += a.y; ts.z += a.z; ts.w += a.w;
                ts2.x += b1.x; ts2.y += b1.y; ts2.z += b1.z; ts2.w += b1.w;
            }
            float inv = 1.0f / (float)NB;
            float4 g4 = *(const float4*)(gamma + tid * 4);
            float4 bt = *(const float4*)(beta  + tid * 4);
            float4 sc, bi;
            float m;
            m = ts.x * inv; sc.x = g4.x * rsqrtf(ts2.x * inv - m * m + 1e-5f); bi.x = bt.x - m * sc.x;
            m = ts.y * inv; sc.y = g4.y * rsqrtf(ts2.y * inv - m * m + 1e-5f); bi.y = bt.y - m * sc.y;
            m = ts.z * inv; sc.z = g4.z * rsqrtf(ts2.z * inv - m * m + 1e-5f); bi.z = bt.z - m * sc.z;
            m = ts.w * inv; sc.w = g4.w * rsqrtf(ts2.w * inv - m * m + 1e-5f); bi.w = bt.w - m * sc.w;
            *(float4*)(ssc + tid * 4) = sc;
            *(float4*)(sbi + tid * 4) = bi;
        }
        __syncthreads();
    }

    // ---- post phase 3: apply BN + ReLU from registers ----
    {
        float4 sc4 = *(const float4*)(ssc + oq * 4);
        float4 bi4 = *(const float4*)(sbi + oq * 4);
        #pragma unroll
        for (int q = 0; q < 4; ++q) {
            int idx = base4 + q * 128 + tid;
            float4 p = pv[q], r;
            r.x = fmaxf(fmaf(p.x, sc4.x, bi4.x), 0.0f);
            r.y = fmaxf(fmaf(p.y, sc4.y, bi4.y), 0.0f);
            r.z = fmaxf(fmaf(p.z, sc4.z, bi4.z), 0.0f);
            r.w = fmaxf(fmaf(p.w, sc4.w, bi4.w), 0.0f);
            *((float4*)out + idx) = r;
        }
    }
}

// ---------------- launch ----------------
extern "C" void kernel_launch(void* const* d_in, const int* in_sizes, int n_in,
                              void* d_out, int out_size) {
    (void)in_sizes; (void)n_in; (void)out_size;
    const float* pts   = (const float*)d_in[0];
    const float* trans = (const float*)d_in[1];
    const float* func  = (const float*)d_in[2];
    const float* kt    = (const float*)d_in[3];
    const float* gamma = (const float*)d_in[4];
    const float* beta  = (const float*)d_in[5];
    float* out = (float*)d_out;

    cudaFuncSetAttribute(k_main, cudaFuncAttributeMaxDynamicSharedMemorySize, 98304);

    k_prepE<<<256, 512>>>(pts, trans, kt);
    k_main<<<256, 128, 98304>>>(out, gamma, beta, func);
}

// round 15
// speedup vs baseline: 1.5975x; 1.5975x over previous
#include <cuda_runtime.h>
#include <cuda_fp16.h>
#include <cstdint>

#define B_    8
#define N_    1024
#define T_    8
#define CIN   64
#define CO    64
#define COLS  512          // T_ * CO
#define NB    (B_ * N_)    // 8192
#define L2E   1.4426950408889634f     // log2(e)
#define NEGH  (-0.72134752044448170f) // -0.5*log2(e)

// ---------------- scratch (static device arrays; no allocation) ----------------
static __device__ __align__(16) float g_rspart[4][NB];      // rowsum partials (k-quarters)
static __device__ __align__(16) float g_cf[NB * T_];        // [b][n][t] exp(-ptd - tsq/2)
static __device__ __align__(16) float g_u [NB * T_];        // [b][n][t] exp(+ptd)
static __device__ __align__(16) float g_kB[CIN * COLS];     // [c][t*64+o]
// E as fp16 m16n8k16 A-fragments: [b][nt(8)][u(64)][mt(8)][lane(32)] uint4
static __device__ __align__(16) uint4 g_E4h[B_ * 8 * 64 * 256];
// Ht as fp16 B-fragments: [b][ch2(2)][u(64)][n8g(32)][lane(32)] uint2
static __device__ __align__(16) uint2 g_Hth[B_ * 2 * 64 * 32 * 32];
static __device__ __align__(16) float g_preP[4][NB * CO];   // per-ch partial planes
static __device__ __align__(16) float g_part [256 * CO];
static __device__ __align__(16) float g_part2[256 * CO];
static __device__ int g_ctr;

// ---------------- helpers ----------------
__device__ __forceinline__ float to_tf32(float x) {
    float r;
    asm("cvt.rna.tf32.f32 %0, %1;" : "=f"(r) : "f"(x));
    return r;
}
__device__ __forceinline__ float ex2f(float x) {
    float r;
    asm("ex2.approx.ftz.f32 %0, %1;" : "=f"(r) : "f"(x));
    return r;
}
__device__ __forceinline__ uint32_t h2pack(float lo, float hi) {
    uint32_t r;
    asm("cvt.rn.f16x2.f32 %0, %1, %2;" : "=r"(r) : "f"(hi), "f"(lo));
    return r;
}
__device__ __forceinline__ uint32_t smem_u32(const void* p) {
    uint32_t a;
    asm("{ .reg .u64 t; cvta.to.shared.u64 t, %1; cvt.u32.u64 %0, t; }" : "=r"(a) : "l"(p));
    return a;
}
__device__ __forceinline__ void cp16(uint32_t s, const void* g) {
    asm volatile("cp.async.cg.shared.global [%0], [%1], 16;" :: "r"(s), "l"(g) : "memory");
}
#define CP_COMMIT() asm volatile("cp.async.commit_group;" ::: "memory")
#define CP_WAIT(n)  asm volatile("cp.async.wait_group %0;" :: "n"(n) : "memory")

// mma.sync m16n8k8 tf32 (k_H only)
__device__ __forceinline__ void mma1688(float* c, const uint32_t* a, const uint32_t* b2) {
    asm volatile(
        "mma.sync.aligned.m16n8k8.row.col.f32.tf32.tf32.f32 "
        "{%0,%1,%2,%3}, {%4,%5,%6,%7}, {%8,%9}, {%0,%1,%2,%3};"
        : "+f"(c[0]), "+f"(c[1]), "+f"(c[2]), "+f"(c[3])
        : "r"(a[0]), "r"(a[1]), "r"(a[2]), "r"(a[3]), "r"(b2[0]), "r"(b2[1]));
}
// mma.sync m16n8k16 fp16 with f32 accum (k_main)
__device__ __forceinline__ void mma16816(float* c, const uint4 a, const uint2 b) {
    asm volatile(
        "mma.sync.aligned.m16n8k16.row.col.f32.f16.f16.f32 "
        "{%0,%1,%2,%3}, {%4,%5,%6,%7}, {%8,%9}, {%0,%1,%2,%3};"
        : "+f"(c[0]), "+f"(c[1]), "+f"(c[2]), "+f"(c[3])
        : "r"(a.x), "r"(a.y), "r"(a.z), "r"(a.w), "r"(b.x), "r"(b.y));
}

// ---------------- K0: E gen (fp16 A-frags) + rowsum quarters + cf/u + kB copy --
// grid 256: b = bx>>5, nt = (bx>>2)&7, kq = bx&3 (u units kq*16 .. +15)
__global__ __launch_bounds__(512) void k_prepE(const float* __restrict__ pts,
                                               const float* __restrict__ trans,
                                               const float* __restrict__ kt) {
    __shared__ float4 pts4[N_];
    __shared__ float4 tr4[T_];
    __shared__ float red[128 * 9];

    int bx = blockIdx.x;
    int b  = bx >> 5;
    int nt = (bx >> 2) & 7;
    int kq = bx & 3;
    int n0 = nt * 128;
    int tid = threadIdx.x;

    if (bx == 0 && tid == 0) g_ctr = 0;   // reset barrier counter for k_main

    if (bx < 16) {
        #pragma unroll
        for (int q = 0; q < 4; ++q) {
            int i = bx * 2048 + q * 512 + tid;
            int c = i >> 9;
            int t = (i >> 6) & 7;
            int o = i & 63;
            g_kB[i] = kt[(o * CIN + c) * T_ + t];
        }
    }

    for (int n = tid; n < N_; n += 512) {
        const float* pp = pts + (b * N_ + n) * 3;
        float x = pp[0], y = pp[1], z = pp[2];
        pts4[n] = make_float4(x, y, z, NEGH * (x * x + y * y + z * z));
    }
    if (tid < T_) {
        const float* tp = trans + (b * T_ + tid) * 3;
        float x = tp[0], y = tp[1], z = tp[2];
        tr4[tid] = make_float4(x, y, z, x * x + y * y + z * z);
    }
    __syncthreads();

    int lane = tid & 31;
    int w    = tid >> 5;
    int mt   = w >> 1;
    int upar = w & 1;
    int r    = lane >> 2;
    int cq   = (lane & 3) * 2;

    float4 pr  = pts4[n0 + mt * 16 + r];
    float4 pr8 = pts4[n0 + mt * 16 + r + 8];

    float sum_r = 0.0f, sum_r8 = 0.0f;
    uint4* ebase = g_E4h + (size_t)(b * 8 + nt) * 64 * 256;

    #pragma unroll 4
    for (int i = 0; i < 8; ++i) {
        int u = kq * 16 + upar + 2 * i;
        int m = u * 16 + cq;
        float4 q0 = pts4[m], q1 = pts4[m + 1];
        float4 q8 = pts4[m + 8], q9 = pts4[m + 9];

        float e_r_0  = ex2f(fmaf(fmaf(pr.z, q0.z, fmaf(pr.y, q0.y, pr.x * q0.x)), L2E, pr.w + q0.w));
        float e_r_1  = ex2f(fmaf(fmaf(pr.z, q1.z, fmaf(pr.y, q1.y, pr.x * q1.x)), L2E, pr.w + q1.w));
        float e_r_8  = ex2f(fmaf(fmaf(pr.z, q8.z, fmaf(pr.y, q8.y, pr.x * q8.x)), L2E, pr.w + q8.w));
        float e_r_9  = ex2f(fmaf(fmaf(pr.z, q9.z, fmaf(pr.y, q9.y, pr.x * q9.x)), L2E, pr.w + q9.w));
        float e_s_0  = ex2f(fmaf(fmaf(pr8.z, q0.z, fmaf(pr8.y, q0.y, pr8.x * q0.x)), L2E, pr8.w + q0.w));
        float e_s_1  = ex2f(fmaf(fmaf(pr8.z, q1.z, fmaf(pr8.y, q1.y, pr8.x * q1.x)), L2E, pr8.w + q1.w));
        float e_s_8  = ex2f(fmaf(fmaf(pr8.z, q8.z, fmaf(pr8.y, q8.y, pr8.x * q8.x)), L2E, pr8.w + q8.w));
        float e_s_9  = ex2f(fmaf(fmaf(pr8.z, q9.z, fmaf(pr8.y, q9.y, pr8.x * q9.w)), L2E, pr8.w + q9.w));
        // NOTE: line above must use q9.z in dot product; fixed below
        e_s_9 = ex2f(fmaf(fmaf(pr8.z, q9.z, fmaf(pr8.y, q9.y, pr8.x * q9.x)), L2E, pr8.w + q9.w));

        sum_r  += (e_r_0 + e_r_1) + (e_r_8 + e_r_9);
        sum_r8 += (e_s_0 + e_s_1) + (e_s_8 + e_s_9);

        uint4 frag;
        frag.x = h2pack(e_r_0, e_r_1);
        frag.y = h2pack(e_s_0, e_s_1);
        frag.z = h2pack(e_r_8, e_r_9);
        frag.w = h2pack(e_s_8, e_s_9);
        ebase[(size_t)u * 256 + mt * 32 + lane] = frag;
    }

    int col = upar * 4 + (lane & 3);
    red[(mt * 16 + r    ) * 9 + col] = sum_r;
    red[(mt * 16 + r + 8) * 9 + col] = sum_r8;
    __syncthreads();

    if (tid < 128) {
        float rs = 0.0f;
        #pragma unroll
        for (int c = 0; c < 8; ++c) rs += red[tid * 9 + c];
        g_rspart[kq][b * N_ + n0 + tid] = rs;
        if (kq == 0) {
            float4 pn = pts4[n0 + tid];
            #pragma unroll
            for (int t = 0; t < T_; ++t) {
                float4 tv = tr4[t];
                float ptd = fmaf(pn.z, tv.z, fmaf(pn.y, tv.y, pn.x * tv.x));
                g_cf[(b * N_ + n0 + tid) * T_ + t] = __expf(-ptd - 0.5f * tv.w);
                g_u [(b * N_ + n0 + tid) * T_ + t] = __expf(ptd);
            }
        }
    }
}

// ---------------- K1: Ht via mma.sync tf32, packed to fp16 B-fragments ---------
#define WS_STRIDE 68
#define KB_STRIDE 136
#define HC_STRIDE 132
__global__ __launch_bounds__(256) void k_H(const float* __restrict__ func) {
    extern __shared__ float sm[];
    float* w_s = sm;                        // [128][68]
    float* kBs = sm + 128 * WS_STRIDE;      // [64][136]
    __shared__ float rinv[128];

    int bx = blockIdx.x;
    int b  = bx >> 5;
    int mt = (bx >> 2) & 7;
    int ct = bx & 3;
    int m0 = mt * 128, c0 = ct * 128;
    int tid = threadIdx.x;
    int lane = tid & 31, wid = tid >> 5;
    int mw = wid & 1, nw = wid >> 1;

    if (tid < 128) {
        int idx = b * N_ + m0 + tid;
        rinv[tid] = 1.0f / (g_rspart[0][idx] + g_rspart[1][idx]
                          + g_rspart[2][idx] + g_rspart[3][idx]);
    }
    __syncthreads();

    for (int i = tid; i < 128 * 16; i += 256) {
        int m = i >> 4, c4 = i & 15;
        float4 v = *(const float4*)(func + (b * N_ + m0 + m) * CIN + c4 * 4);
        float r = rinv[m];
        v.x = to_tf32(v.x * r); v.y = to_tf32(v.y * r);
        v.z = to_tf32(v.z * r); v.w = to_tf32(v.w * r);
        *(float4*)(w_s + m * WS_STRIDE + c4 * 4) = v;
    }
    for (int i = tid; i < 64 * 32; i += 256) {
        int c = i >> 5, j = i & 31;
        float4 v = *(const float4*)(g_kB + c * COLS + c0 + j * 4);
        v.x = to_tf32(v.x); v.y = to_tf32(v.y);
        v.z = to_tf32(v.z); v.w = to_tf32(v.w);
        *(float4*)(kBs + c * KB_STRIDE + j * 4) = v;
    }
    __syncthreads();

    float c_[4][4][4];
    #pragma unroll
    for (int i = 0; i < 4; ++i)
        #pragma unroll
        for (int j = 0; j < 4; ++j)
            #pragma unroll
            for (int q = 0; q < 4; ++q) c_[i][j][q] = 0.0f;

    int ar = (lane >> 2), ac = (lane & 3);
    #pragma unroll
    for (int k8 = 0; k8 < 8; ++k8) {
        uint32_t a[4][4];
        #pragma unroll
        for (int mi = 0; mi < 4; ++mi) {
            int row = mw * 64 + mi * 16 + ar;
            int col = k8 * 8 + ac;
            a[mi][0] = __float_as_uint(w_s[row * WS_STRIDE + col]);
            a[mi][1] = __float_as_uint(w_s[(row + 8) * WS_STRIDE + col]);
            a[mi][2] = __float_as_uint(w_s[row * WS_STRIDE + col + 4]);
            a[mi][3] = __float_as_uint(w_s[(row + 8) * WS_STRIDE + col + 4]);
        }
        uint32_t bv[4][2];
        #pragma unroll
        for (int nj = 0; nj < 4; ++nj) {
            int kk = k8 * 8 + ac;
            int col = nw * 32 + nj * 8 + ar;
            bv[nj][0] = __float_as_uint(kBs[kk * KB_STRIDE + col]);
            bv[nj][1] = __float_as_uint(kBs[(kk + 4) * KB_STRIDE + col]);
        }
        #pragma unroll
        for (int mi = 0; mi < 4; ++mi)
            #pragma unroll
            for (int nj = 0; nj < 4; ++nj)
                mma1688(c_[mi][nj], a[mi], bv[nj]);
    }
    __syncthreads();

    #pragma unroll
    for (int mi = 0; mi < 4; ++mi)
        #pragma unroll
        for (int nj = 0; nj < 4; ++nj)
            #pragma unroll
            for (int q = 0; q < 4; ++q) {
                int row = mw * 64 + mi * 16 + ar + ((q >> 1) * 8);
                int col = nw * 32 + nj * 8 + ac * 2 + (q & 1);
                sm[row * HC_STRIDE + col] = c_[mi][nj][q];
            }
    __syncthreads();

    int ty = tid >> 4, tx = tid & 15;
    int jt_g = ct * 16 + tx;
    int t = jt_g >> 3;
    float cf_i[8];
    #pragma unroll
    for (int i = 0; i < 8; ++i)
        cf_i[i] = g_cf[(b * N_ + m0 + ty * 8 + i) * T_ + t];

    int ch2 = ct >> 1;
    int n8g = (ct & 1) * 16 + tx;
    int u   = mt * 8 + (ty >> 1);
    int sel = ty & 1;
    size_t base_idx = ((size_t)((b * 2 + ch2) * 64 + u) * 32 + n8g) * 32;
    char* hb = (char*)g_Hth;

    #pragma unroll
    for (int jj = 0; jj < 8; ++jj) {
        float v[8];
        #pragma unroll
        for (int i = 0; i < 8; ++i)
            v[i] = sm[(ty * 8 + i) * HC_STRIDE + tx * 8 + jj] * cf_i[i];
        #pragma unroll
        for (int ip = 0; ip < 4; ++ip) {
            uint32_t hv = h2pack(v[2 * ip], v[2 * ip + 1]);
            size_t idx = base_idx + jj * 4 + ip;
            *(uint32_t*)(hb + idx * 8 + sel * 4) = hv;
        }
    }
}

// ---------------- K2: fp16 HMMA GEMM + device barrier + fused BN/ReLU ----------
// grid 256 (2 CTA/SM, ALL resident -> counter barrier safe): b=bx>>5, nt=(bx>>2)&7,
// ch=bx&3.  CTA M128 x N128 x K1024, 128 thr, warp tile 64x64, smem 96KB.
#define RST 68
__global__ __launch_bounds__(128, 2) void k_main(float* __restrict__ out,
                                                 const float* __restrict__ gamma,
                                                 const float* __restrict__ beta) {
    extern __shared__ float sm[];
    uint32_t sbase = smem_u32(sm);

    int bx = blockIdx.x;
    int b  = bx >> 5;
    int nt = (bx >> 2) & 7;
    int ch = bx & 3;
    int ch2 = ch >> 1, chH = ch & 1;
    int n0 = nt * 128;
    int tid = threadIdx.x;
    int wid = tid >> 5, lane = tid & 31;
    int mw = wid & 1, nw = wid >> 1;
    int skew = (bx & 1) * 8;

    const char* EA = (const char*)(g_E4h + (size_t)(b * 8 + nt) * 64 * 256);
    const char* HB = (const char*)(g_Hth + (size_t)(b * 2 + ch2) * 64 * 1024) + chH * 4096;
    uint32_t sA = sbase;              // 3 x 16384 B
    uint32_t sB = sbase + 49152;      // 3 x 16384 B

    auto issue = [&](int s) {
        int buf = s % 3;
        int u0 = ((s + skew) & 15) * 4;
        #pragma unroll
        for (int p = 0; p < 8; ++p) {
            int idx = p * 128 + tid;
            int ul = idx >> 8, rem = (idx & 255) * 16;
            cp16(sA + buf * 16384 + idx * 16, EA + (size_t)(u0 + ul) * 4096 + rem);
            cp16(sB + buf * 16384 + idx * 16, HB + (size_t)(u0 + ul) * 8192 + rem);
        }
        CP_COMMIT();
    };

    issue(0); issue(1);

    float c_[4][8][4];
    #pragma unroll
    for (int i = 0; i < 4; ++i)
        #pragma unroll
        for (int j = 0; j < 8; ++j)
            #pragma unroll
            for (int q = 0; q < 4; ++q) c_[i][j][q] = 0.0f;

    for (int kc = 0; kc < 16; ++kc) {
        if (kc < 14) { CP_WAIT(1); } else { CP_WAIT(0); }
        __syncthreads();

        int buf = kc % 3;
        const uint4* Au = (const uint4*)(sm) + buf * 1024;
        const uint2* Bu = (const uint2*)(sm + 12288) + buf * 2048;

        #pragma unroll
        for (int ul = 0; ul < 4; ++ul) {
            uint4 a[4];
            #pragma unroll
            for (int mi = 0; mi < 4; ++mi)
                a[mi] = Au[(ul * 8 + mw * 4 + mi) * 32 + lane];
            uint2 bv[8];
            #pragma unroll
            for (int nj = 0; nj < 8; ++nj)
                bv[nj] = Bu[(ul * 16 + nw * 8 + nj) * 32 + lane];
            #pragma unroll
            for (int mi = 0; mi < 4; ++mi)
                #pragma unroll
                for (int nj = 0; nj < 8; ++nj)
                    mma16816(c_[mi][nj], a[mi], bv[nj]);
        }

        if (kc < 14) issue(kc + 2);
    }

    // ---- GEMM epilogue: scale by u_t, smem-reduce the CTA's two t's, write plane
    __syncthreads();
    {
        int t = ch * 2 + nw;
        float* red = sm + mw * 64 * RST;

        if (nw == 0) {
            #pragma unroll
            for (int mi = 0; mi < 4; ++mi) {
                #pragma unroll
                for (int ro = 0; ro < 2; ++ro) {
                    int rloc = mi * 16 + (lane >> 2) + ro * 8;
                    float u = g_u[(b * N_ + n0 + mw * 64 + rloc) * T_ + t];
                    #pragma unroll
                    for (int nj = 0; nj < 8; ++nj) {
                        float2 v;
                        v.x = c_[mi][nj][ro * 2 + 0] * u;
                        v.y = c_[mi][nj][ro * 2 + 1] * u;
                        *(float2*)(red + rloc * RST + nj * 8 + (lane & 3) * 2) = v;
                    }
                }
            }
        }
        __syncthreads();
        if (nw == 1) {
            #pragma unroll
            for (int mi = 0; mi < 4; ++mi) {
                #pragma unroll
                for (int ro = 0; ro < 2; ++ro) {
                    int rloc = mi * 16 + (lane >> 2) + ro * 8;
                    int n = n0 + mw * 64 + rloc;
                    float u = g_u[(b * N_ + n) * T_ + t];
                    float* dst = g_preP[ch] + (size_t)(b * N_ + n) * CO + (lane & 3) * 2;
                    #pragma unroll
                    for (int nj = 0; nj < 8; ++nj) {
                        float2 p = *(const float2*)(red + rloc * RST + nj * 8 + (lane & 3) * 2);
                        float2 v;
                        v.x = fmaf(c_[mi][nj][ro * 2 + 0], u, p.x);
                        v.y = fmaf(c_[mi][nj][ro * 2 + 1], u, p.y);
                        *(float2*)(dst + nj * 8) = v;
                    }
                }
            }
        }
    }

    // ---- device-wide barrier #1: all plane writes done ----
    __threadfence();
    __syncthreads();
    if (tid == 0) {
        atomicAdd(&g_ctr, 1);
        while (atomicAdd(&g_ctr, 0) < 256) { __nanosleep(32); }
    }
    __syncthreads();

    // ---- post phase 1: sum 4 planes for this block's 32 rows (L2-hot) ----
    float4* shs  = (float4*)sm;          // [16][8]
    float4* shs2 = (float4*)sm + 128;    // [16][8]
    float*  ssc  = sm + 1024;
    float*  sbi  = sm + 1088;
    int base4 = bx * 512;                // float4 index of this block's 32 rows
    int oq  = tid & 15;                  // channel quad
    int grp = tid >> 4;                  // 0..7

    const float4* P0 = (const float4*)g_preP[0];
    const float4* P1 = (const float4*)g_preP[1];
    const float4* P2 = (const float4*)g_preP[2];
    const float4* P3 = (const float4*)g_preP[3];

    float4 pv[4];
    float4 s  = make_float4(0.f, 0.f, 0.f, 0.f);
    float4 s2 = make_float4(0.f, 0.f, 0.f, 0.f);
    #pragma unroll
    for (int q = 0; q < 4; ++q) {
        int idx = base4 + q * 128 + tid;
        float4 a  = __ldcg(&P0[idx]);
        float4 b1 = __ldcg(&P1[idx]);
        float4 c  = __ldcg(&P2[idx]);
        float4 d  = __ldcg(&P3[idx]);
        float4 p;
        p.x = (a.x + b1.x) + (c.x + d.x);
        p.y = (a.y + b1.y) + (c.y + d.y);
        p.z = (a.z + b1.z) + (c.z + d.z);
        p.w = (a.w + b1.w) + (c.w + d.w);
        pv[q] = p;
        s.x += p.x; s.y += p.y; s.z += p.z; s.w += p.w;
        s2.x += p.x * p.x; s2.y += p.y * p.y; s2.z += p.z * p.z; s2.w += p.w * p.w;
    }
    shs [oq * 8 + grp] = s;
    shs2[oq * 8 + grp] = s2;
    __syncthreads();
    if (tid < 16) {
        float4 ts  = shs [tid * 8], ts2 = shs2[tid * 8];
        #pragma unroll
        for (int g = 1; g < 8; ++g) {
            float4 a = shs[tid * 8 + g], b1 = shs2[tid * 8 + g];
            ts.x += a.x; ts.y += a.y; ts.z += a.z; ts.w += a.w;
            ts2.x += b1.x; ts2.y += b1.y; ts2.z += b1.z; ts2.w += b1.w;
        }
        ((float4*)g_part )[bx * 16 + tid] = ts;
        ((float4*)g_part2)[bx * 16 + tid] = ts2;
    }

    // ---- device-wide barrier #2: all stat partials done ----
    __threadfence();
    __syncthreads();
    if (tid == 0) {
        atomicAdd(&g_ctr, 1);
        while (atomicAdd(&g_ctr, 0) < 512) { __nanosleep(32); }
    }
    __syncthreads();

    // ---- post phase 2: reduce 256 partials, compute scale/bias ----
    {
        const float4* G1 = (const float4*)g_part;
        const float4* G2 = (const float4*)g_part2;
        float4 ps  = make_float4(0.f, 0.f, 0.f, 0.f);
        float4 ps2 = make_float4(0.f, 0.f, 0.f, 0.f);
        for (int i = grp; i < 256; i += 8) {
            float4 a  = __ldcg(&G1[i * 16 + oq]);
            float4 b1 = __ldcg(&G2[i * 16 + oq]);
            ps.x += a.x; ps.y += a.y; ps.z += a.z; ps.w += a.w;
            ps2.x += b1.x; ps2.y += b1.y; ps2.z += b1.z; ps2.w += b1.w;
        }
        shs [oq * 8 + grp] = ps;
        shs2[oq * 8 + grp] = ps2;
        __syncthreads();
        if (tid < 16) {
            float4 ts  = shs [tid * 8], ts2 = shs2[tid * 8];
            #pragma unroll
            for (int g = 1; g < 8; ++g) {
                float4 a = shs[tid * 8 + g], b1 = shs2[tid * 8 + g];
                ts.x += a.x; ts.y += a.y; ts.z += a.z; ts.w += a.w;
                ts2.x += b1.x; ts2.y += b1.y; ts2.z += b1.z; ts2.w += b1.w;
            }
            float inv = 1.0f / (float)NB;
            float4 g4 = *(const float4*)(gamma + tid * 4);
            float4 bt = *(const float4*)(beta  + tid * 4);
            float4 sc, bi;
            float m;
            m = ts.x * inv; sc.x = g4.x * rsqrtf(ts2.x * inv - m * m + 1e-5f); bi.x = bt.x - m * sc.x;
            m = ts.y * inv; sc.y = g4.y * rsqrtf(ts2.y * inv - m * m + 1e-5f); bi.y = bt.y - m * sc.y;
            m = ts.z * inv; sc.z = g4.z * rsqrtf(ts2.z * inv - m * m + 1e-5f); bi.z = bt.z - m * sc.z;
            m = ts.w * inv; sc.w = g4.w * rsqrtf(ts2.w * inv - m * m + 1e-5f); bi.w = bt.w - m * sc.w;
            *(float4*)(ssc + tid * 4) = sc;
            *(float4*)(sbi + tid * 4) = bi;
        }
        __syncthreads();
    }

    // ---- post phase 3: apply BN + ReLU from registers ----
    {
        float4 sc4 = *(const float4*)(ssc + oq * 4);
        float4 bi4 = *(const float4*)(sbi + oq * 4);
        #pragma unroll
        for (int q = 0; q < 4; ++q) {
            int idx = base4 + q * 128 + tid;
            float4 p = pv[q], r;
            r.x = fmaxf(fmaf(p.x, sc4.x, bi4.x), 0.0f);
            r.y = fmaxf(fmaf(p.y, sc4.y, bi4.y), 0.0f);
            r.z = fmaxf(fmaf(p.z, sc4.z, bi4.z), 0.0f);
            r.w = fmaxf(fmaf(p.w, sc4.w, bi4.w), 0.0f);
            *((float4*)out + idx) = r;
        }
    }
}

// ---------------- launch ----------------
extern "C" void kernel_launch(void* const* d_in, const int* in_sizes, int n_in,
                              void* d_out, int out_size) {
    (void)in_sizes; (void)n_in; (void)out_size;
    const float* pts   = (const float*)d_in[0];
    const float* trans = (const float*)d_in[1];
    const float* func  = (const float*)d_in[2];
    const float* kt    = (const float*)d_in[3];
    const float* gamma = (const float*)d_in[4];
    const float* beta  = (const float*)d_in[5];
    float* out = (float*)d_out;

    cudaFuncSetAttribute(k_main, cudaFuncAttributeMaxDynamicSharedMemorySize, 98304);
    cudaFuncSetAttribute(k_H,    cudaFuncAttributeMaxDynamicSharedMemorySize, 69632);

    k_prepE<<<256, 512>>>(pts, trans, kt);
    k_H<<<256, 256, 69632>>>(func);
    k_main<<<256, 128, 98304>>>(out, gamma, beta);
}

// round 16
// speedup vs baseline: 1.6644x; 1.0419x over previous
#include <cuda_runtime.h>
#include <cuda_fp16.h>
#include <cstdint>

#define B_    8
#define N_    1024
#define T_    8
#define CIN   64
#define CO    64
#define COLS  512          // T_ * CO
#define NB    (B_ * N_)    // 8192
#define L2E   1.4426950408889634f     // log2(e)
#define NEGH  (-0.72134752044448170f) // -0.5*log2(e)

// ---------------- scratch (static device arrays; no allocation) ----------------
static __device__ __align__(16) float g_rspart[4][NB];      // rowsum partials (k-quarters)
static __device__ __align__(16) float g_cf[NB * T_];        // [b][n][t] exp(-ptd - tsq/2)
static __device__ __align__(16) float g_u [NB * T_];        // [b][n][t] exp(+ptd)
static __device__ __align__(16) float g_kB[CIN * COLS];     // [c][t*64+o]
// E as fp16 m16n8k16 A-fragments: [b][nt(8)][u(64)][mt(8)][lane(32)] uint4
static __device__ __align__(16) uint4 g_E4h[B_ * 8 * 64 * 256];
// Ht as fp16 B-fragments, PAIRED layout:
// byte = [b][ch2]*512KB + u*8192 + chH*4096 + pair*512 + lane*16 + po*8 + sel*4
static __device__ __align__(16) uint2 g_Hth[B_ * 2 * 64 * 32 * 32];
static __device__ __align__(16) float g_preP[4][NB * CO];   // per-ch partial planes
static __device__ __align__(16) float g_part [256 * CO];
static __device__ __align__(16) float g_part2[256 * CO];
static __device__ int g_ctr;

// ---------------- helpers ----------------
__device__ __forceinline__ float to_tf32(float x) {
    float r;
    asm("cvt.rna.tf32.f32 %0, %1;" : "=f"(r) : "f"(x));
    return r;
}
__device__ __forceinline__ float ex2f(float x) {
    float r;
    asm("ex2.approx.ftz.f32 %0, %1;" : "=f"(r) : "f"(x));
    return r;
}
__device__ __forceinline__ uint32_t h2pack(float lo, float hi) {
    uint32_t r;
    asm("cvt.rn.f16x2.f32 %0, %1, %2;" : "=r"(r) : "f"(hi), "f"(lo));
    return r;
}
__device__ __forceinline__ uint32_t smem_u32(const void* p) {
    uint32_t a;
    asm("{ .reg .u64 t; cvta.to.shared.u64 t, %1; cvt.u32.u64 %0, t; }" : "=r"(a) : "l"(p));
    return a;
}
__device__ __forceinline__ void cp16(uint32_t s, const void* g) {
    asm volatile("cp.async.cg.shared.global [%0], [%1], 16;" :: "r"(s), "l"(g) : "memory");
}
#define CP_COMMIT() asm volatile("cp.async.commit_group;" ::: "memory")
#define CP_WAIT(n)  asm volatile("cp.async.wait_group %0;" :: "n"(n) : "memory")

// mma.sync m16n8k8 tf32 (k_H only)
__device__ __forceinline__ void mma1688(float* c, const uint32_t* a, const uint32_t* b2) {
    asm volatile(
        "mma.sync.aligned.m16n8k8.row.col.f32.tf32.tf32.f32 "
        "{%0,%1,%2,%3}, {%4,%5,%6,%7}, {%8,%9}, {%0,%1,%2,%3};"
        : "+f"(c[0]), "+f"(c[1]), "+f"(c[2]), "+f"(c[3])
        : "r"(a[0]), "r"(a[1]), "r"(a[2]), "r"(a[3]), "r"(b2[0]), "r"(b2[1]));
}
// mma.sync m16n8k16 fp16 with f32 accum (k_main)
__device__ __forceinline__ void mma16816(float* c, const uint4 a, const uint2 b) {
    asm volatile(
        "mma.sync.aligned.m16n8k16.row.col.f32.f16.f16.f32 "
        "{%0,%1,%2,%3}, {%4,%5,%6,%7}, {%8,%9}, {%0,%1,%2,%3};"
        : "+f"(c[0]), "+f"(c[1]), "+f"(c[2]), "+f"(c[3])
        : "r"(a.x), "r"(a.y), "r"(a.z), "r"(a.w), "r"(b.x), "r"(b.y));
}

// ---------------- K0: E gen (fp16 A-frags) + rowsum quarters + cf/u + kB copy --
// grid 256: b = bx>>5, nt = (bx>>2)&7, kq = bx&3 (u units kq*16 .. +15)
__global__ __launch_bounds__(512) void k_prepE(const float* __restrict__ pts,
                                               const float* __restrict__ trans,
                                               const float* __restrict__ kt) {
    __shared__ float4 pts4[N_];
    __shared__ float4 tr4[T_];
    __shared__ float red[128 * 9];

    int bx = blockIdx.x;
    int b  = bx >> 5;
    int nt = (bx >> 2) & 7;
    int kq = bx & 3;
    int n0 = nt * 128;
    int tid = threadIdx.x;

    if (bx == 0 && tid == 0) g_ctr = 0;   // reset barrier counter for k_main

    if (bx < 16) {
        #pragma unroll
        for (int q = 0; q < 4; ++q) {
            int i = bx * 2048 + q * 512 + tid;
            int c = i >> 9;
            int t = (i >> 6) & 7;
            int o = i & 63;
            g_kB[i] = kt[(o * CIN + c) * T_ + t];
        }
    }

    for (int n = tid; n < N_; n += 512) {
        const float* pp = pts + (b * N_ + n) * 3;
        float x = pp[0], y = pp[1], z = pp[2];
        pts4[n] = make_float4(x, y, z, NEGH * (x * x + y * y + z * z));
    }
    if (tid < T_) {
        const float* tp = trans + (b * T_ + tid) * 3;
        float x = tp[0], y = tp[1], z = tp[2];
        tr4[tid] = make_float4(x, y, z, x * x + y * y + z * z);
    }
    __syncthreads();

    int lane = tid & 31;
    int w    = tid >> 5;
    int mt   = w >> 1;
    int upar = w & 1;
    int r    = lane >> 2;
    int cq   = (lane & 3) * 2;

    float4 pr  = pts4[n0 + mt * 16 + r];
    float4 pr8 = pts4[n0 + mt * 16 + r + 8];

    float sum_r = 0.0f, sum_r8 = 0.0f;
    uint4* ebase = g_E4h + (size_t)(b * 8 + nt) * 64 * 256;

    #pragma unroll 4
    for (int i = 0; i < 8; ++i) {
        int u = kq * 16 + upar + 2 * i;
        int m = u * 16 + cq;
        float4 q0 = pts4[m], q1 = pts4[m + 1];
        float4 q8 = pts4[m + 8], q9 = pts4[m + 9];

        float e_r_0  = ex2f(fmaf(fmaf(pr.z, q0.z, fmaf(pr.y, q0.y, pr.x * q0.x)), L2E, pr.w + q0.w));
        float e_r_1  = ex2f(fmaf(fmaf(pr.z, q1.z, fmaf(pr.y, q1.y, pr.x * q1.x)), L2E, pr.w + q1.w));
        float e_r_8  = ex2f(fmaf(fmaf(pr.z, q8.z, fmaf(pr.y, q8.y, pr.x * q8.x)), L2E, pr.w + q8.w));
        float e_r_9  = ex2f(fmaf(fmaf(pr.z, q9.z, fmaf(pr.y, q9.y, pr.x * q9.x)), L2E, pr.w + q9.w));
        float e_s_0  = ex2f(fmaf(fmaf(pr8.z, q0.z, fmaf(pr8.y, q0.y, pr8.x * q0.x)), L2E, pr8.w + q0.w));
        float e_s_1  = ex2f(fmaf(fmaf(pr8.z, q1.z, fmaf(pr8.y, q1.y, pr8.x * q1.x)), L2E, pr8.w + q1.w));
        float e_s_8  = ex2f(fmaf(fmaf(pr8.z, q8.z, fmaf(pr8.y, q8.y, pr8.x * q8.x)), L2E, pr8.w + q8.w));
        float e_s_9  = ex2f(fmaf(fmaf(pr8.z, q9.z, fmaf(pr8.y, q9.y, pr8.x * q9.x)), L2E, pr8.w + q9.w));

        sum_r  += (e_r_0 + e_r_1) + (e_r_8 + e_r_9);
        sum_r8 += (e_s_0 + e_s_1) + (e_s_8 + e_s_9);

        uint4 frag;
        frag.x = h2pack(e_r_0, e_r_1);
        frag.y = h2pack(e_s_0, e_s_1);
        frag.z = h2pack(e_r_8, e_r_9);
        frag.w = h2pack(e_s_8, e_s_9);
        ebase[(size_t)u * 256 + mt * 32 + lane] = frag;
    }

    int col = upar * 4 + (lane & 3);
    red[(mt * 16 + r    ) * 9 + col] = sum_r;
    red[(mt * 16 + r + 8) * 9 + col] = sum_r8;
    __syncthreads();

    if (tid < 128) {
        float rs = 0.0f;
        #pragma unroll
        for (int c = 0; c < 8; ++c) rs += red[tid * 9 + c];
        g_rspart[kq][b * N_ + n0 + tid] = rs;
        if (kq == 0) {
            float4 pn = pts4[n0 + tid];
            #pragma unroll
            for (int t = 0; t < T_; ++t) {
                float4 tv = tr4[t];
                float ptd = fmaf(pn.z, tv.z, fmaf(pn.y, tv.y, pn.x * tv.x));
                g_cf[(b * N_ + n0 + tid) * T_ + t] = __expf(-ptd - 0.5f * tv.w);
                g_u [(b * N_ + n0 + tid) * T_ + t] = __expf(ptd);
            }
        }
    }
}

// ---------------- K1: Ht via mma.sync tf32, packed to PAIRED fp16 B-fragments --
#define WS_STRIDE 68
#define KB_STRIDE 136
#define HC_STRIDE 132
__global__ __launch_bounds__(256) void k_H(const float* __restrict__ func) {
    extern __shared__ float sm[];
    float* w_s = sm;                        // [128][68]
    float* kBs = sm + 128 * WS_STRIDE;      // [64][136]
    __shared__ float rinv[128];

    int bx = blockIdx.x;
    int b  = bx >> 5;
    int mt = (bx >> 2) & 7;
    int ct = bx & 3;
    int m0 = mt * 128, c0 = ct * 128;
    int tid = threadIdx.x;
    int lane = tid & 31, wid = tid >> 5;
    int mw = wid & 1, nw = wid >> 1;

    if (tid < 128) {
        int idx = b * N_ + m0 + tid;
        rinv[tid] = 1.0f / (g_rspart[0][idx] + g_rspart[1][idx]
                          + g_rspart[2][idx] + g_rspart[3][idx]);
    }
    __syncthreads();

    for (int i = tid; i < 128 * 16; i += 256) {
        int m = i >> 4, c4 = i & 15;
        float4 v = *(const float4*)(func + (b * N_ + m0 + m) * CIN + c4 * 4);
        float r = rinv[m];
        v.x = to_tf32(v.x * r); v.y = to_tf32(v.y * r);
        v.z = to_tf32(v.z * r); v.w = to_tf32(v.w * r);
        *(float4*)(w_s + m * WS_STRIDE + c4 * 4) = v;
    }
    for (int i = tid; i < 64 * 32; i += 256) {
        int c = i >> 5, j = i & 31;
        float4 v = *(const float4*)(g_kB + c * COLS + c0 + j * 4);
        v.x = to_tf32(v.x); v.y = to_tf32(v.y);
        v.z = to_tf32(v.z); v.w = to_tf32(v.w);
        *(float4*)(kBs + c * KB_STRIDE + j * 4) = v;
    }
    __syncthreads();

    float c_[4][4][4];
    #pragma unroll
    for (int i = 0; i < 4; ++i)
        #pragma unroll
        for (int j = 0; j < 4; ++j)
            #pragma unroll
            for (int q = 0; q < 4; ++q) c_[i][j][q] = 0.0f;

    int ar = (lane >> 2), ac = (lane & 3);
    #pragma unroll
    for (int k8 = 0; k8 < 8; ++k8) {
        uint32_t a[4][4];
        #pragma unroll
        for (int mi = 0; mi < 4; ++mi) {
            int row = mw * 64 + mi * 16 + ar;
            int col = k8 * 8 + ac;
            a[mi][0] = __float_as_uint(w_s[row * WS_STRIDE + col]);
            a[mi][1] = __float_as_uint(w_s[(row + 8) * WS_STRIDE + col]);
            a[mi][2] = __float_as_uint(w_s[row * WS_STRIDE + col + 4]);
            a[mi][3] = __float_as_uint(w_s[(row + 8) * WS_STRIDE + col + 4]);
        }
        uint32_t bv[4][2];
        #pragma unroll
        for (int nj = 0; nj < 4; ++nj) {
            int kk = k8 * 8 + ac;
            int col = nw * 32 + nj * 8 + ar;
            bv[nj][0] = __float_as_uint(kBs[kk * KB_STRIDE + col]);
            bv[nj][1] = __float_as_uint(kBs[(kk + 4) * KB_STRIDE + col]);
        }
        #pragma unroll
        for (int mi = 0; mi < 4; ++mi)
            #pragma unroll
            for (int nj = 0; nj < 4; ++nj)
                mma1688(c_[mi][nj], a[mi], bv[nj]);
    }
    __syncthreads();

    #pragma unroll
    for (int mi = 0; mi < 4; ++mi)
        #pragma unroll
        for (int nj = 0; nj < 4; ++nj)
            #pragma unroll
            for (int q = 0; q < 4; ++q) {
                int row = mw * 64 + mi * 16 + ar + ((q >> 1) * 8);
                int col = nw * 32 + nj * 8 + ac * 2 + (q & 1);
                sm[row * HC_STRIDE + col] = c_[mi][nj][q];
            }
    __syncthreads();

    int ty = tid >> 4, tx = tid & 15;
    int jt_g = ct * 16 + tx;
    int t = jt_g >> 3;
    float cf_i[8];
    #pragma unroll
    for (int i = 0; i < 8; ++i)
        cf_i[i] = g_cf[(b * N_ + m0 + ty * 8 + i) * T_ + t];

    // PAIRED layout write:
    // byte = ((b*2+ch2)*64+u)*8192 + chH*4096 + (tx>>1)*512 + lane*16 + (tx&1)*8 + sel*4
    int ch2 = ct >> 1;
    int chH = ct & 1;
    int u   = mt * 8 + (ty >> 1);
    int sel = ty & 1;
    char* hb = (char*)g_Hth;
    size_t ubase = ((size_t)((b * 2 + ch2) * 64 + u)) * 8192
                 + (size_t)chH * 4096 + (tx >> 1) * 512 + (tx & 1) * 8 + sel * 4;

    #pragma unroll
    for (int jj = 0; jj < 8; ++jj) {
        float v[8];
        #pragma unroll
        for (int i = 0; i < 8; ++i)
            v[i] = sm[(ty * 8 + i) * HC_STRIDE + tx * 8 + jj] * cf_i[i];
        #pragma unroll
        for (int ip = 0; ip < 4; ++ip) {
            uint32_t hv = h2pack(v[2 * ip], v[2 * ip + 1]);
            *(uint32_t*)(hb + ubase + (size_t)(jj * 4 + ip) * 16) = hv;
        }
    }
}

// ---------------- K2: fp16 HMMA GEMM + device barrier + fused BN/ReLU ----------
// grid 256 (2 CTA/SM; co-resident pair = (i, i+148) -> bit7 distinguishes them)
#define RST 68
__global__ __launch_bounds__(128, 2) void k_main(float* __restrict__ out,
                                                 const float* __restrict__ gamma,
                                                 const float* __restrict__ beta) {
    extern __shared__ float sm[];
    uint32_t sbase = smem_u32(sm);

    int bx = blockIdx.x;
    int b  = bx >> 5;
    int nt = (bx >> 2) & 7;
    int ch = bx & 3;
    int ch2 = ch >> 1, chH = ch & 1;
    int n0 = nt * 128;
    int tid = threadIdx.x;
    int wid = tid >> 5, lane = tid & 31;
    int mw = wid & 1, nw = wid >> 1;
    int hi = (bx >> 7) & 1;           // differs across every co-resident pair
    int skew = hi * 8;

    // phase-stagger: offset the second co-resident CTA by ~half a chunk
    if (hi) {
        float d0 = 1.0f + tid * 1e-7f;
        #pragma unroll 1
        for (int i = 0; i < 384; ++i)
            asm volatile("fma.rn.f32 %0, %0, 0f3F800001, 0f33800000;" : "+f"(d0));
    }

    const char* EA = (const char*)(g_E4h + (size_t)(b * 8 + nt) * 64 * 256);
    const char* HB = (const char*)(g_Hth + (size_t)(b * 2 + ch2) * 64 * 1024) + chH * 4096;
    uint32_t sA = sbase;              // 3 x 16384 B
    uint32_t sB = sbase + 49152;      // 3 x 16384 B

    auto issue = [&](int s) {
        int buf = s % 3;
        int u0 = ((s + skew) & 15) * 4;
        #pragma unroll
        for (int p = 0; p < 8; ++p) {
            int idx = p * 128 + tid;
            int ul = idx >> 8, rem = (idx & 255) * 16;
            cp16(sA + buf * 16384 + idx * 16, EA + (size_t)(u0 + ul) * 4096 + rem);
            cp16(sB + buf * 16384 + idx * 16, HB + (size_t)(u0 + ul) * 8192 + rem);
        }
        CP_COMMIT();
    };

    issue(0); issue(1);

    float c_[4][8][4];
    #pragma unroll
    for (int i = 0; i < 4; ++i)
        #pragma unroll
        for (int j = 0; j < 8; ++j)
            #pragma unroll
            for (int q = 0; q < 4; ++q) c_[i][j][q] = 0.0f;

    for (int kc = 0; kc < 16; ++kc) {
        if (kc < 14) { CP_WAIT(1); } else { CP_WAIT(0); }
        __syncthreads();

        int buf = kc % 3;
        const uint4* Au  = (const uint4*)(sm) + buf * 1024;
        const uint4* Bu4 = (const uint4*)(sm + 12288) + buf * 1024;

        #pragma unroll
        for (int ul = 0; ul < 4; ++ul) {
            uint4 a[4];
            #pragma unroll
            for (int mi = 0; mi < 4; ++mi)
                a[mi] = Au[(ul * 8 + mw * 4 + mi) * 32 + lane];
            uint2 bv[8];
            #pragma unroll
            for (int njp = 0; njp < 4; ++njp) {
                uint4 v = Bu4[(ul * 8 + nw * 4 + njp) * 32 + lane];
                bv[2 * njp]     = make_uint2(v.x, v.y);
                bv[2 * njp + 1] = make_uint2(v.z, v.w);
            }
            #pragma unroll
            for (int mi = 0; mi < 4; ++mi)
                #pragma unroll
                for (int nj = 0; nj < 8; ++nj)
                    mma16816(c_[mi][nj], a[mi], bv[nj]);
        }

        if (kc < 14) issue(kc + 2);
    }

    // ---- GEMM epilogue: scale by u_t, smem-reduce the CTA's two t's, write plane
    __syncthreads();
    {
        int t = ch * 2 + nw;
        float* red = sm + mw * 64 * RST;

        if (nw == 0) {
            #pragma unroll
            for (int mi = 0; mi < 4; ++mi) {
                #pragma unroll
                for (int ro = 0; ro < 2; ++ro) {
                    int rloc = mi * 16 + (lane >> 2) + ro * 8;
                    float u = g_u[(b * N_ + n0 + mw * 64 + rloc) * T_ + t];
                    #pragma unroll
                    for (int nj = 0; nj < 8; ++nj) {
                        float2 v;
                        v.x = c_[mi][nj][ro * 2 + 0] * u;
                        v.y = c_[mi][nj][ro * 2 + 1] * u;
                        *(float2*)(red + rloc * RST + nj * 8 + (lane & 3) * 2) = v;
                    }
                }
            }
        }
        __syncthreads();
        if (nw == 1) {
            #pragma unroll
            for (int mi = 0; mi < 4; ++mi) {
                #pragma unroll
                for (int ro = 0; ro < 2; ++ro) {
                    int rloc = mi * 16 + (lane >> 2) + ro * 8;
                    int n = n0 + mw * 64 + rloc;
                    float u = g_u[(b * N_ + n) * T_ + t];
                    float* dst = g_preP[ch] + (size_t)(b * N_ + n) * CO + (lane & 3) * 2;
                    #pragma unroll
                    for (int nj = 0; nj < 8; ++nj) {
                        float2 p = *(const float2*)(red + rloc * RST + nj * 8 + (lane & 3) * 2);
                        float2 v;
                        v.x = fmaf(c_[mi][nj][ro * 2 + 0], u, p.x);
                        v.y = fmaf(c_[mi][nj][ro * 2 + 1], u, p.y);
                        *(float2*)(dst + nj * 8) = v;
                    }
                }
            }
        }
    }

    // ---- device-wide barrier #1: all plane writes done ----
    __threadfence();
    __syncthreads();
    if (tid == 0) {
        atomicAdd(&g_ctr, 1);
        while (atomicAdd(&g_ctr, 0) < 256) { __nanosleep(32); }
    }
    __syncthreads();

    // ---- post phase 1: sum 4 planes for this block's 32 rows (L2-hot) ----
    float4* shs  = (float4*)sm;          // [16][8]
    float4* shs2 = (float4*)sm + 128;    // [16][8]
    float*  ssc  = sm + 1024;
    float*  sbi  = sm + 1088;
    int base4 = bx * 512;                // float4 index of this block's 32 rows
    int oq  = tid & 15;                  // channel quad
    int grp = tid >> 4;                  // 0..7

    const float4* P0 = (const float4*)g_preP[0];
    const float4* P1 = (const float4*)g_preP[1];
    const float4* P2 = (const float4*)g_preP[2];
    const float4* P3 = (const float4*)g_preP[3];

    float4 pv[4];
    float4 s  = make_float4(0.f, 0.f, 0.f, 0.f);
    float4 s2 = make_float4(0.f, 0.f, 0.f, 0.f);
    #pragma unroll
    for (int q = 0; q < 4; ++q) {
        int idx = base4 + q * 128 + tid;
        float4 a  = __ldcg(&P0[idx]);
        float4 b1 = __ldcg(&P1[idx]);
        float4 c  = __ldcg(&P2[idx]);
        float4 d  = __ldcg(&P3[idx]);
        float4 p;
        p.x = (a.x + b1.x) + (c.x + d.x);
        p.y = (a.y + b1.y) + (c.y + d.y);
        p.z = (a.z + b1.z) + (c.z + d.z);
        p.w = (a.w + b1.w) + (c.w + d.w);
        pv[q] = p;
        s.x += p.x; s.y += p.y; s.z += p.z; s.w += p.w;
        s2.x += p.x * p.x; s2.y += p.y * p.y; s2.z += p.z * p.z; s2.w += p.w * p.w;
    }
    shs [oq * 8 + grp] = s;
    shs2[oq * 8 + grp] = s2;
    __syncthreads();
    if (tid < 16) {
        float4 ts  = shs [tid * 8], ts2 = shs2[tid * 8];
        #pragma unroll
        for (int g = 1; g < 8; ++g) {
            float4 a = shs[tid * 8 + g], b1 = shs2[tid * 8 + g];
            ts.x += a.x; ts.y += a.y; ts.z += a.z; ts.w += a.w;
            ts2.x += b1.x; ts2.y += b1.y; ts2.z += b1.z; ts2.w += b1.w;
        }
        ((float4*)g_part )[bx * 16 + tid] = ts;
        ((float4*)g_part2)[bx * 16 + tid] = ts2;
    }

    // ---- device-wide barrier #2: all stat partials done ----
    __threadfence();
    __syncthreads();
    if (tid == 0) {
        atomicAdd(&g_ctr, 1);
        while (atomicAdd(&g_ctr, 0) < 512) { __nanosleep(32); }
    }
    __syncthreads();

    // ---- post phase 2: reduce 256 partials, compute scale/bias ----
    {
        const float4* G1 = (const float4*)g_part;
        const float4* G2 = (const float4*)g_part2;
        float4 ps  = make_float4(0.f, 0.f, 0.f, 0.f);
        float4 ps2 = make_float4(0.f, 0.f, 0.f, 0.f);
        for (int i = grp; i < 256; i += 8) {
            float4 a  = __ldcg(&G1[i * 16 + oq]);
            float4 b1 = __ldcg(&G2[i * 16 + oq]);
            ps.x += a.x; ps.y += a.y; ps.z += a.z; ps.w += a.w;
            ps2.x += b1.x; ps2.y += b1.y; ps2.z += b1.z; ps2.w += b1.w;
        }
        shs [oq * 8 + grp] = ps;
        shs2[oq * 8 + grp] = ps2;
        __syncthreads();
        if (tid < 16) {
            float4 ts  = shs [tid * 8], ts2 = shs2[tid * 8];
            #pragma unroll
            for (int g = 1; g < 8; ++g) {
                float4 a = shs[tid * 8 + g], b1 = shs2[tid * 8 + g];
                ts.x += a.x; ts.y += a.y; ts.z += a.z; ts.w += a.w;
                ts2.x += b1.x; ts2.y += b1.y; ts2.z += b1.z; ts2.w += b1.w;
            }
            float inv = 1.0f / (float)NB;
            float4 g4 = *(const float4*)(gamma + tid * 4);
            float4 bt = *(const float4*)(beta  + tid * 4);
            float4 sc, bi;
            float m;
            m = ts.x * inv; sc.x = g4.x * rsqrtf(ts2.x * inv - m * m + 1e-5f); bi.x = bt.x - m * sc.x;
            m = ts.y * inv; sc.y = g4.y * rsqrtf(ts2.y * inv - m * m + 1e-5f); bi.y = bt.y - m * sc.y;
            m = ts.z * inv; sc.z = g4.z * rsqrtf(ts2.z * inv - m * m + 1e-5f); bi.z = bt.z - m * sc.z;
            m = ts.w * inv; sc.w = g4.w * rsqrtf(ts2.w * inv - m * m + 1e-5f); bi.w = bt.w - m * sc.w;
            *(float4*)(ssc + tid * 4) = sc;
            *(float4*)(sbi + tid * 4) = bi;
        }
        __syncthreads();
    }

    // ---- post phase 3: apply BN + ReLU from registers ----
    {
        float4 sc4 = *(const float4*)(ssc + oq * 4);
        float4 bi4 = *(const float4*)(sbi + oq * 4);
        #pragma unroll
        for (int q = 0; q < 4; ++q) {
            int idx = base4 + q * 128 + tid;
            float4 p = pv[q], r;
            r.x = fmaxf(fmaf(p.x, sc4.x, bi4.x), 0.0f);
            r.y = fmaxf(fmaf(p.y, sc4.y, bi4.y), 0.0f);
            r.z = fmaxf(fmaf(p.z, sc4.z, bi4.z), 0.0f);
            r.w = fmaxf(fmaf(p.w, sc4.w, bi4.w), 0.0f);
            *((float4*)out + idx) = r;
        }
    }
}

// ---------------- launch ----------------
extern "C" void kernel_launch(void* const* d_in, const int* in_sizes, int n_in,
                              void* d_out, int out_size) {
    (void)in_sizes; (void)n_in; (void)out_size;
    const float* pts   = (const float*)d_in[0];
    const float* trans = (const float*)d_in[1];
    const float* func  = (const float*)d_in[2];
    const float* kt    = (const float*)d_in[3];
    const float* gamma = (const float*)d_in[4];
    const float* beta  = (const float*)d_in[5];
    float* out = (float*)d_out;

    cudaFuncSetAttribute(k_main, cudaFuncAttributeMaxDynamicSharedMemorySize, 98304);
    cudaFuncSetAttribute(k_H,    cudaFuncAttributeMaxDynamicSharedMemorySize, 69632);

    k_prepE<<<256, 512>>>(pts, trans, kt);
    k_H<<<256, 256, 69632>>>(func);
    k_main<<<256, 128, 98304>>>(out, gamma, beta);
}

// round 17
// speedup vs baseline: 1.6778x; 1.0081x over previous
#include <cuda_runtime.h>
#include <cuda_fp16.h>
#include <cstdint>

#define B_    8
#define N_    1024
#define T_    8
#define CIN   64
#define CO    64
#define COLS  512          // T_ * CO
#define NB    (B_ * N_)    // 8192
#define L2E   1.4426950408889634f     // log2(e)
#define NEGH  (-0.72134752044448170f) // -0.5*log2(e)

// ---------------- scratch (static device arrays; no allocation) ----------------
static __device__ __align__(16) float g_rspart[4][NB];      // rowsum partials (k-quarters)
static __device__ __align__(16) float g_cf[NB * T_];        // [b][n][t] exp(-ptd - tsq/2)
static __device__ __align__(16) float g_u [NB * T_];        // [b][n][t] exp(+ptd)
static __device__ __align__(16) float g_kB[CIN * COLS];     // [c][t*64+o]
// E as fp16 m16n8k16 A-fragments: [b][nt(8)][u(64)][mt(8)][lane(32)] uint4
static __device__ __align__(16) uint4 g_E4h[B_ * 8 * 64 * 256];
// Ht as fp16 B-fragments, PAIRED layout:
// byte = [b][ch2]*512KB + u*8192 + chH*4096 + pair*512 + lane*16 + po*8 + sel*4
static __device__ __align__(16) uint2 g_Hth[B_ * 2 * 64 * 32 * 32];
static __device__ __align__(16) float g_preP[4][NB * CO];   // per-ch partial planes
static __device__ __align__(16) float g_part [256 * CO];
static __device__ __align__(16) float g_part2[256 * CO];
static __device__ int g_ctr;

// ---------------- helpers ----------------
__device__ __forceinline__ float ex2f(float x) {
    float r;
    asm("ex2.approx.ftz.f32 %0, %1;" : "=f"(r) : "f"(x));
    return r;
}
__device__ __forceinline__ uint32_t h2pack(float lo, float hi) {
    uint32_t r;
    asm("cvt.rn.f16x2.f32 %0, %1, %2;" : "=r"(r) : "f"(hi), "f"(lo));
    return r;
}
__device__ __forceinline__ uint32_t smem_u32(const void* p) {
    uint32_t a;
    asm("{ .reg .u64 t; cvta.to.shared.u64 t, %1; cvt.u32.u64 %0, t; }" : "=r"(a) : "l"(p));
    return a;
}
__device__ __forceinline__ void cp16(uint32_t s, const void* g) {
    asm volatile("cp.async.cg.shared.global [%0], [%1], 16;" :: "r"(s), "l"(g) : "memory");
}
#define CP_COMMIT() asm volatile("cp.async.commit_group;" ::: "memory")
#define CP_WAIT(n)  asm volatile("cp.async.wait_group %0;" :: "n"(n) : "memory")

// mma.sync m16n8k8 tf32 (k_H only)
__device__ __forceinline__ void mma1688(float* c, const uint32_t* a, const uint32_t* b2) {
    asm volatile(
        "mma.sync.aligned.m16n8k8.row.col.f32.tf32.tf32.f32 "
        "{%0,%1,%2,%3}, {%4,%5,%6,%7}, {%8,%9}, {%0,%1,%2,%3};"
        : "+f"(c[0]), "+f"(c[1]), "+f"(c[2]), "+f"(c[3])
        : "r"(a[0]), "r"(a[1]), "r"(a[2]), "r"(a[3]), "r"(b2[0]), "r"(b2[1]));
}
// mma.sync m16n8k16 fp16 with f32 accum (k_main)
__device__ __forceinline__ void mma16816(float* c, const uint4 a, const uint2 b) {
    asm volatile(
        "mma.sync.aligned.m16n8k16.row.col.f32.f16.f16.f32 "
        "{%0,%1,%2,%3}, {%4,%5,%6,%7}, {%8,%9}, {%0,%1,%2,%3};"
        : "+f"(c[0]), "+f"(c[1]), "+f"(c[2]), "+f"(c[3])
        : "r"(a.x), "r"(a.y), "r"(a.z), "r"(a.w), "r"(b.x), "r"(b.y));
}

// ---------------- K0: E gen (fp16 A-frags) + rowsum quarters + cf/u + kB copy --
// grid 256: b = bx>>5, nt = (bx>>2)&7, kq = bx&3 (u units kq*16 .. +15)
__global__ __launch_bounds__(512) void k_prepE(const float* __restrict__ pts,
                                               const float* __restrict__ trans,
                                               const float* __restrict__ kt) {
    __shared__ float4 pts4[N_];
    __shared__ float4 tr4[T_];
    __shared__ float red[128 * 9];

    int bx = blockIdx.x;
    int b  = bx >> 5;
    int nt = (bx >> 2) & 7;
    int kq = bx & 3;
    int n0 = nt * 128;
    int tid = threadIdx.x;

    if (bx == 0 && tid == 0) g_ctr = 0;   // reset barrier counter for k_main

    if (bx < 16) {
        #pragma unroll
        for (int q = 0; q < 4; ++q) {
            int i = bx * 2048 + q * 512 + tid;
            int c = i >> 9;
            int t = (i >> 6) & 7;
            int o = i & 63;
            g_kB[i] = kt[(o * CIN + c) * T_ + t];
        }
    }

    for (int n = tid; n < N_; n += 512) {
        const float* pp = pts + (b * N_ + n) * 3;
        float x = pp[0], y = pp[1], z = pp[2];
        pts4[n] = make_float4(x, y, z, NEGH * (x * x + y * y + z * z));
    }
    if (tid < T_) {
        const float* tp = trans + (b * T_ + tid) * 3;
        float x = tp[0], y = tp[1], z = tp[2];
        tr4[tid] = make_float4(x, y, z, x * x + y * y + z * z);
    }
    __syncthreads();

    int lane = tid & 31;
    int w    = tid >> 5;
    int mt   = w >> 1;
    int upar = w & 1;
    int r    = lane >> 2;
    int cq   = (lane & 3) * 2;

    float4 pr  = pts4[n0 + mt * 16 + r];
    float4 pr8 = pts4[n0 + mt * 16 + r + 8];

    float sum_r = 0.0f, sum_r8 = 0.0f;
    uint4* ebase = g_E4h + (size_t)(b * 8 + nt) * 64 * 256;

    #pragma unroll 4
    for (int i = 0; i < 8; ++i) {
        int u = kq * 16 + upar + 2 * i;
        int m = u * 16 + cq;
        float4 q0 = pts4[m], q1 = pts4[m + 1];
        float4 q8 = pts4[m + 8], q9 = pts4[m + 9];

        float e_r_0  = ex2f(fmaf(fmaf(pr.z, q0.z, fmaf(pr.y, q0.y, pr.x * q0.x)), L2E, pr.w + q0.w));
        float e_r_1  = ex2f(fmaf(fmaf(pr.z, q1.z, fmaf(pr.y, q1.y, pr.x * q1.x)), L2E, pr.w + q1.w));
        float e_r_8  = ex2f(fmaf(fmaf(pr.z, q8.z, fmaf(pr.y, q8.y, pr.x * q8.x)), L2E, pr.w + q8.w));
        float e_r_9  = ex2f(fmaf(fmaf(pr.z, q9.z, fmaf(pr.y, q9.y, pr.x * q9.x)), L2E, pr.w + q9.w));
        float e_s_0  = ex2f(fmaf(fmaf(pr8.z, q0.z, fmaf(pr8.y, q0.y, pr8.x * q0.x)), L2E, pr8.w + q0.w));
        float e_s_1  = ex2f(fmaf(fmaf(pr8.z, q1.z, fmaf(pr8.y, q1.y, pr8.x * q1.x)), L2E, pr8.w + q1.w));
        float e_s_8  = ex2f(fmaf(fmaf(pr8.z, q8.z, fmaf(pr8.y, q8.y, pr8.x * q8.x)), L2E, pr8.w + q8.w));
        float e_s_9  = ex2f(fmaf(fmaf(pr8.z, q9.z, fmaf(pr8.y, q9.y, pr8.x * q9.x)), L2E, pr8.w + q9.w));

        sum_r  += (e_r_0 + e_r_1) + (e_r_8 + e_r_9);
        sum_r8 += (e_s_0 + e_s_1) + (e_s_8 + e_s_9);

        uint4 frag;
        frag.x = h2pack(e_r_0, e_r_1);
        frag.y = h2pack(e_s_0, e_s_1);
        frag.z = h2pack(e_r_8, e_r_9);
        frag.w = h2pack(e_s_8, e_s_9);
        ebase[(size_t)u * 256 + mt * 32 + lane] = frag;
    }

    int col = upar * 4 + (lane & 3);
    red[(mt * 16 + r    ) * 9 + col] = sum_r;
    red[(mt * 16 + r + 8) * 9 + col] = sum_r8;
    __syncthreads();

    if (tid < 128) {
        float rs = 0.0f;
        #pragma unroll
        for (int c = 0; c < 8; ++c) rs += red[tid * 9 + c];
        g_rspart[kq][b * N_ + n0 + tid] = rs;
        if (kq == 0) {
            float4 pn = pts4[n0 + tid];
            #pragma unroll
            for (int t = 0; t < T_; ++t) {
                float4 tv = tr4[t];
                float ptd = fmaf(pn.z, tv.z, fmaf(pn.y, tv.y, pn.x * tv.x));
                g_cf[(b * N_ + n0 + tid) * T_ + t] = __expf(-ptd - 0.5f * tv.w);
                g_u [(b * N_ + n0 + tid) * T_ + t] = __expf(ptd);
            }
        }
    }
}

// ---------------- K1: Ht via mma.sync tf32 (cp.async staging, rinv folded late) -
#define WS_STRIDE 68
#define KB_STRIDE 136
#define HC_STRIDE 132
__global__ __launch_bounds__(256) void k_H(const float* __restrict__ func) {
    extern __shared__ float sm[];
    float* w_s = sm;                        // [128][68]  raw func tile
    float* kBs = sm + 128 * WS_STRIDE;      // [64][136]  raw kB tile
    __shared__ float rinv[128];

    int bx = blockIdx.x;
    int b  = bx >> 5;
    int mt = (bx >> 2) & 7;
    int ct = bx & 3;
    int m0 = mt * 128, c0 = ct * 128;
    int tid = threadIdx.x;
    int lane = tid & 31, wid = tid >> 5;
    int mw = wid & 1, nw = wid >> 1;

    // async staging: func 2048 chunks + kB 2048 chunks, 16 per thread
    {
        uint32_t ws_a = smem_u32(w_s);
        uint32_t kb_a = smem_u32(kBs);
        const char* fsrc = (const char*)(func + (size_t)(b * N_ + m0) * CIN);
        const char* ksrc = (const char*)(g_kB + c0);
        #pragma unroll
        for (int p = 0; p < 8; ++p) {
            int idx = p * 256 + tid;       // 0..2047
            int m  = idx >> 4, c4 = idx & 15;
            cp16(ws_a + m * (WS_STRIDE * 4) + c4 * 16, fsrc + (size_t)m * 256 + c4 * 16);
            int c  = idx >> 5, j  = idx & 31;
            cp16(kb_a + c * (KB_STRIDE * 4) + j * 16, ksrc + (size_t)c * (COLS * 4) + j * 16);
        }
        CP_COMMIT();
    }

    // overlap: compute rinv while cp.async in flight
    if (tid < 128) {
        int idx = b * N_ + m0 + tid;
        rinv[tid] = 1.0f / (g_rspart[0][idx] + g_rspart[1][idx]
                          + g_rspart[2][idx] + g_rspart[3][idx]);
    }
    CP_WAIT(0);
    __syncthreads();

    float c_[4][4][4];
    #pragma unroll
    for (int i = 0; i < 4; ++i)
        #pragma unroll
        for (int j = 0; j < 4; ++j)
            #pragma unroll
            for (int q = 0; q < 4; ++q) c_[i][j][q] = 0.0f;

    int ar = (lane >> 2), ac = (lane & 3);
    #pragma unroll
    for (int k8 = 0; k8 < 8; ++k8) {
        uint32_t a[4][4];
        #pragma unroll
        for (int mi = 0; mi < 4; ++mi) {
            int row = mw * 64 + mi * 16 + ar;
            int col = k8 * 8 + ac;
            a[mi][0] = __float_as_uint(w_s[row * WS_STRIDE + col]);
            a[mi][1] = __float_as_uint(w_s[(row + 8) * WS_STRIDE + col]);
            a[mi][2] = __float_as_uint(w_s[row * WS_STRIDE + col + 4]);
            a[mi][3] = __float_as_uint(w_s[(row + 8) * WS_STRIDE + col + 4]);
        }
        uint32_t bv[4][2];
        #pragma unroll
        for (int nj = 0; nj < 4; ++nj) {
            int kk = k8 * 8 + ac;
            int col = nw * 32 + nj * 8 + ar;
            bv[nj][0] = __float_as_uint(kBs[kk * KB_STRIDE + col]);
            bv[nj][1] = __float_as_uint(kBs[(kk + 4) * KB_STRIDE + col]);
        }
        #pragma unroll
        for (int mi = 0; mi < 4; ++mi)
            #pragma unroll
            for (int nj = 0; nj < 4; ++nj)
                mma1688(c_[mi][nj], a[mi], bv[nj]);
    }
    __syncthreads();   // staging dead; reuse smem as canonical tile

    #pragma unroll
    for (int mi = 0; mi < 4; ++mi)
        #pragma unroll
        for (int nj = 0; nj < 4; ++nj)
            #pragma unroll
            for (int q = 0; q < 4; ++q) {
                int row = mw * 64 + mi * 16 + ar + ((q >> 1) * 8);
                int col = nw * 32 + nj * 8 + ac * 2 + (q & 1);
                sm[row * HC_STRIDE + col] = c_[mi][nj][q];
            }
    __syncthreads();

    int ty = tid >> 4, tx = tid & 15;
    int jt_g = ct * 16 + tx;
    int t = jt_g >> 3;
    float cfr[8];
    #pragma unroll
    for (int i = 0; i < 8; ++i)
        cfr[i] = g_cf[(b * N_ + m0 + ty * 8 + i) * T_ + t] * rinv[ty * 8 + i];

    // PAIRED layout write:
    // byte = ((b*2+ch2)*64+u)*8192 + chH*4096 + (tx>>1)*512 + lane*16 + (tx&1)*8 + sel*4
    int ch2 = ct >> 1;
    int chH = ct & 1;
    int u   = mt * 8 + (ty >> 1);
    int sel = ty & 1;
    char* hb = (char*)g_Hth;
    size_t ubase = ((size_t)((b * 2 + ch2) * 64 + u)) * 8192
                 + (size_t)chH * 4096 + (tx >> 1) * 512 + (tx & 1) * 8 + sel * 4;

    #pragma unroll
    for (int jj = 0; jj < 8; ++jj) {
        float v[8];
        #pragma unroll
        for (int i = 0; i < 8; ++i)
            v[i] = sm[(ty * 8 + i) * HC_STRIDE + tx * 8 + jj] * cfr[i];
        #pragma unroll
        for (int ip = 0; ip < 4; ++ip) {
            uint32_t hv = h2pack(v[2 * ip], v[2 * ip + 1]);
            *(uint32_t*)(hb + ubase + (size_t)(jj * 4 + ip) * 16) = hv;
        }
    }
}

// ---------------- K2: fp16 HMMA GEMM + device barrier + fused BN/ReLU ----------
// grid 256 (2 CTA/SM; co-resident pair = (i, i+148) -> bit7 distinguishes them)
#define RST 68
__global__ __launch_bounds__(128, 2) void k_main(float* __restrict__ out,
                                                 const float* __restrict__ gamma,
                                                 const float* __restrict__ beta) {
    extern __shared__ float sm[];
    uint32_t sbase = smem_u32(sm);

    int bx = blockIdx.x;
    int b  = bx >> 5;
    int nt = (bx >> 2) & 7;
    int ch = bx & 3;
    int ch2 = ch >> 1, chH = ch & 1;
    int n0 = nt * 128;
    int tid = threadIdx.x;
    int wid = tid >> 5, lane = tid & 31;
    int mw = wid & 1, nw = wid >> 1;
    int hi = (bx >> 7) & 1;           // differs across every co-resident pair
    int skew = hi * 8;

    // phase-stagger: offset the second co-resident CTA by ~half a chunk
    if (hi) {
        float d0 = 1.0f + tid * 1e-7f;
        #pragma unroll 1
        for (int i = 0; i < 384; ++i)
            asm volatile("fma.rn.f32 %0, %0, 0f3F800001, 0f33800000;" : "+f"(d0));
    }

    const char* EA = (const char*)(g_E4h + (size_t)(b * 8 + nt) * 64 * 256);
    const char* HB = (const char*)(g_Hth + (size_t)(b * 2 + ch2) * 64 * 1024) + chH * 4096;
    uint32_t sA = sbase;              // 3 x 16384 B
    uint32_t sB = sbase + 49152;      // 3 x 16384 B

    auto issue = [&](int s) {
        int buf = s % 3;
        int u0 = ((s + skew) & 15) * 4;
        #pragma unroll
        for (int p = 0; p < 8; ++p) {
            int idx = p * 128 + tid;
            int ul = idx >> 8, rem = (idx & 255) * 16;
            cp16(sA + buf * 16384 + idx * 16, EA + (size_t)(u0 + ul) * 4096 + rem);
            cp16(sB + buf * 16384 + idx * 16, HB + (size_t)(u0 + ul) * 8192 + rem);
        }
        CP_COMMIT();
    };

    issue(0); issue(1);

    float c_[4][8][4];
    #pragma unroll
    for (int i = 0; i < 4; ++i)
        #pragma unroll
        for (int j = 0; j < 8; ++j)
            #pragma unroll
            for (int q = 0; q < 4; ++q) c_[i][j][q] = 0.0f;

    for (int kc = 0; kc < 16; ++kc) {
        if (kc < 14) { CP_WAIT(1); } else { CP_WAIT(0); }
        __syncthreads();

        int buf = kc % 3;
        const uint4* Au  = (const uint4*)(sm) + buf * 1024;
        const uint4* Bu4 = (const uint4*)(sm + 12288) + buf * 1024;

        #pragma unroll
        for (int ul = 0; ul < 4; ++ul) {
            uint4 a[4];
            #pragma unroll
            for (int mi = 0; mi < 4; ++mi)
                a[mi] = Au[(ul * 8 + mw * 4 + mi) * 32 + lane];
            uint2 bv[8];
            #pragma unroll
            for (int njp = 0; njp < 4; ++njp) {
                uint4 v = Bu4[(ul * 8 + nw * 4 + njp) * 32 + lane];
                bv[2 * njp]     = make_uint2(v.x, v.y);
                bv[2 * njp + 1] = make_uint2(v.z, v.w);
            }
            #pragma unroll
            for (int mi = 0; mi < 4; ++mi)
                #pragma unroll
                for (int nj = 0; nj < 8; ++nj)
                    mma16816(c_[mi][nj], a[mi], bv[nj]);
        }

        if (kc < 14) issue(kc + 2);
    }

    // ---- GEMM epilogue: scale by u_t, smem-reduce the CTA's two t's, write plane
    __syncthreads();
    {
        int t = ch * 2 + nw;
        float* red = sm + mw * 64 * RST;

        if (nw == 0) {
            #pragma unroll
            for (int mi = 0; mi < 4; ++mi) {
                #pragma unroll
                for (int ro = 0; ro < 2; ++ro) {
                    int rloc = mi * 16 + (lane >> 2) + ro * 8;
                    float u = g_u[(b * N_ + n0 + mw * 64 + rloc) * T_ + t];
                    #pragma unroll
                    for (int nj = 0; nj < 8; ++nj) {
                        float2 v;
                        v.x = c_[mi][nj][ro * 2 + 0] * u;
                        v.y = c_[mi][nj][ro * 2 + 1] * u;
                        *(float2*)(red + rloc * RST + nj * 8 + (lane & 3) * 2) = v;
                    }
                }
            }
        }
        __syncthreads();
        if (nw == 1) {
            #pragma unroll
            for (int mi = 0; mi < 4; ++mi) {
                #pragma unroll
                for (int ro = 0; ro < 2; ++ro) {
                    int rloc = mi * 16 + (lane >> 2) + ro * 8;
                    int n = n0 + mw * 64 + rloc;
                    float u = g_u[(b * N_ + n) * T_ + t];
                    float* dst = g_preP[ch] + (size_t)(b * N_ + n) * CO + (lane & 3) * 2;
                    #pragma unroll
                    for (int nj = 0; nj < 8; ++nj) {
                        float2 p = *(const float2*)(red + rloc * RST + nj * 8 + (lane & 3) * 2);
                        float2 v;
                        v.x = fmaf(c_[mi][nj][ro * 2 + 0], u, p.x);
                        v.y = fmaf(c_[mi][nj][ro * 2 + 1], u, p.y);
                        *(float2*)(dst + nj * 8) = v;
                    }
                }
            }
        }
    }

    // ---- device-wide barrier #1: all plane writes done ----
    __threadfence();
    __syncthreads();
    if (tid == 0) {
        atomicAdd(&g_ctr, 1);
        while (atomicAdd(&g_ctr, 0) < 256) { __nanosleep(32); }
    }
    __syncthreads();

    // ---- post phase 1: sum 4 planes for this block's 32 rows (L2-hot) ----
    float4* shs  = (float4*)sm;          // [16][8]
    float4* shs2 = (float4*)sm + 128;    // [16][8]
    float*  ssc  = sm + 1024;
    float*  sbi  = sm + 1088;
    int base4 = bx * 512;                // float4 index of this block's 32 rows
    int oq  = tid & 15;                  // channel quad
    int grp = tid >> 4;                  // 0..7

    const float4* P0 = (const float4*)g_preP[0];
    const float4* P1 = (const float4*)g_preP[1];
    const float4* P2 = (const float4*)g_preP[2];
    const float4* P3 = (const float4*)g_preP[3];

    float4 pv[4];
    float4 s  = make_float4(0.f, 0.f, 0.f, 0.f);
    float4 s2 = make_float4(0.f, 0.f, 0.f, 0.f);
    #pragma unroll
    for (int q = 0; q < 4; ++q) {
        int idx = base4 + q * 128 + tid;
        float4 a  = __ldcg(&P0[idx]);
        float4 b1 = __ldcg(&P1[idx]);
        float4 c  = __ldcg(&P2[idx]);
        float4 d  = __ldcg(&P3[idx]);
        float4 p;
        p.x = (a.x + b1.x) + (c.x + d.x);
        p.y = (a.y + b1.y) + (c.y + d.y);
        p.z = (a.z + b1.z) + (c.z + d.z);
        p.w = (a.w + b1.w) + (c.w + d.w);
        pv[q] = p;
        s.x += p.x; s.y += p.y; s.z += p.z; s.w += p.w;
        s2.x += p.x * p.x; s2.y += p.y * p.y; s2.z += p.z * p.z; s2.w += p.w * p.w;
    }
    shs [oq * 8 + grp] = s;
    shs2[oq * 8 + grp] = s2;
    __syncthreads();
    if (tid < 16) {
        float4 ts  = shs [tid * 8], ts2 = shs2[tid * 8];
        #pragma unroll
        for (int g = 1; g < 8; ++g) {
            float4 a = shs[tid * 8 + g], b1 = shs2[tid * 8 + g];
            ts.x += a.x; ts.y += a.y; ts.z += a.z; ts.w += a.w;
            ts2.x += b1.x; ts2.y += b1.y; ts2.z += b1.z; ts2.w += b1.w;
        }
        ((float4*)g_part )[bx * 16 + tid] = ts;
        ((float4*)g_part2)[bx * 16 + tid] = ts2;
    }

    // ---- device-wide barrier #2: all stat partials done ----
    __threadfence();
    __syncthreads();
    if (tid == 0) {
        atomicAdd(&g_ctr, 1);
        while (atomicAdd(&g_ctr, 0) < 512) { __nanosleep(32); }
    }
    __syncthreads();

    // ---- post phase 2: reduce 256 partials, compute scale/bias ----
    {
        const float4* G1 = (const float4*)g_part;
        const float4* G2 = (const float4*)g_part2;
        float4 ps  = make_float4(0.f, 0.f, 0.f, 0.f);
        float4 ps2 = make_float4(0.f, 0.f, 0.f, 0.f);
        for (int i = grp; i < 256; i += 8) {
            float4 a  = __ldcg(&G1[i * 16 + oq]);
            float4 b1 = __ldcg(&G2[i * 16 + oq]);
            ps.x += a.x; ps.y += a.y; ps.z += a.z; ps.w += a.w;
            ps2.x += b1.x; ps2.y += b1.y; ps2.z += b1.z; ps2.w += b1.w;
        }
        shs [oq * 8 + grp] = ps;
        shs2[oq * 8 + grp] = ps2;
        __syncthreads();
        if (tid < 16) {
            float4 ts  = shs [tid * 8], ts2 = shs2[tid * 8];
            #pragma unroll
            for (int g = 1; g < 8; ++g) {
                float4 a = shs[tid * 8 + g], b1 = shs2[tid * 8 + g];
                ts.x += a.x; ts.y += a.y; ts.z += a.z; ts.w += a.w;
                ts2.x += b1.x; ts2.y += b1.y; ts2.z += b1.z; ts2.w += b1.w;
            }
            float inv = 1.0f / (float)NB;
            float4 g4 = *(const float4*)(gamma + tid * 4);
            float4 bt = *(const float4*)(beta  + tid * 4);
            float4 sc, bi;
            float m;
            m = ts.x * inv; sc.x = g4.x * rsqrtf(ts2.x * inv - m * m + 1e-5f); bi.x = bt.x - m * sc.x;
            m = ts.y * inv; sc.y = g4.y * rsqrtf(ts2.y * inv - m * m + 1e-5f); bi.y = bt.y - m * sc.y;
            m = ts.z * inv; sc.z = g4.z * rsqrtf(ts2.z * inv - m * m + 1e-5f); bi.z = bt.z - m * sc.z;
            m = ts.w * inv; sc.w = g4.w * rsqrtf(ts2.w * inv - m * m + 1e-5f); bi.w = bt.w - m * sc.w;
            *(float4*)(ssc + tid * 4) = sc;
            *(float4*)(sbi + tid * 4) = bi;
        }
        __syncthreads();
    }

    // ---- post phase 3: apply BN + ReLU from registers ----
    {
        float4 sc4 = *(const float4*)(ssc + oq * 4);
        float4 bi4 = *(const float4*)(sbi + oq * 4);
        #pragma unroll
        for (int q = 0; q < 4; ++q) {
            int idx = base4 + q * 128 + tid;
            float4 p = pv[q], r;
            r.x = fmaxf(fmaf(p.x, sc4.x, bi4.x), 0.0f);
            r.y = fmaxf(fmaf(p.y, sc4.y, bi4.y), 0.0f);
            r.z = fmaxf(fmaf(p.z, sc4.z, bi4.z), 0.0f);
            r.w = fmaxf(fmaf(p.w, sc4.w, bi4.w), 0.0f);
            *((float4*)out + idx) = r;
        }
    }
}

// ---------------- launch ----------------
extern "C" void kernel_launch(void* const* d_in, const int* in_sizes, int n_in,
                              void* d_out, int out_size) {
    (void)in_sizes; (void)n_in; (void)out_size;
    const float* pts   = (const float*)d_in[0];
    const float* trans = (const float*)d_in[1];
    const float* func  = (const float*)d_in[2];
    const float* kt    = (const float*)d_in[3];
    const float* gamma = (const float*)d_in[4];
    const float* beta  = (const float*)d_in[5];
    float* out = (float*)d_out;

    cudaFuncSetAttribute(k_main, cudaFuncAttributeMaxDynamicSharedMemorySize, 98304);
    cudaFuncSetAttribute(k_H,    cudaFuncAttributeMaxDynamicSharedMemorySize, 69632);

    k_prepE<<<256, 512>>>(pts, trans, kt);
    k_H<<<256, 256, 69632>>>(func);
    k_main<<<256, 128, 98304>>>(out, gamma, beta);
}